// round 1
// baseline (speedup 1.0000x reference)
#include <cuda_runtime.h>
#include <math.h>

// Problem constants
#define BI 256      // I
#define BH 512      // H
#define BC 1024     // C
#define G4 2048     // 4H
#define TYN 32
#define TXN 128
#define BB 32       // batch

#define NBLK 148
#define NTHR 256
#define SPAD 1540                  // 1536 + 4 pad (banking + f4 alignment)
#define SMEM_BYTES (32 * SPAD * 4) // 197120

// ---------------- device scratch ----------------
__device__ float g_pctx[(size_t)TXN * BB * BC];   // [4096][1024]
__device__ float g_x[(size_t)TYN * BB * G4];      // [1024][2048]
__device__ float g_hcur[BB * BH];
__device__ float g_ccur[BB * BH];
__device__ float g_h1[BB * BH];
__device__ float g_c1[BB * BH];
__device__ float g_pre1[BB * G4];
__device__ float g_pre2[BB * G4];
__device__ float g_hproj[BB * BC];
__device__ float g_score[TXN * BB];
__device__ float g_atted[BB * BC];
__device__ unsigned g_barcnt;  // monotonic, generation-based barrier

__device__ __forceinline__ float sigf(float x) { return 1.f / (1.f + __expf(-x)); }

// ---------------- grid barrier ----------------
__device__ __forceinline__ void gbar() {
    __syncthreads();
    if (threadIdx.x == 0) {
        __threadfence();
        unsigned arr = atomicAdd(&g_barcnt, 1u);
        unsigned target = (arr / gridDim.x + 1u) * gridDim.x;
        while (atomicAdd(&g_barcnt, 0u) < target) {
            __nanosleep(64);
        }
        __threadfence();
    }
    __syncthreads();
}

// ---------------- SGEMM (NT): C[m][n] = sum_k A[m*K+k]*Bm[n*K+k] ----------------
// BM=BN=128, BK=8, 256 threads, 8x8 per thread. M%128==0, N%128==0, K%8==0.
__global__ void __launch_bounds__(256) sgemm_nt(int sel,
                                                const float* __restrict__ A,
                                                const float* __restrict__ Bm,
                                                int M, int N, int K) {
    float* Cm = (sel == 0) ? g_pctx : g_x;
    __shared__ float As[8][128];
    __shared__ float Bs[8][128];
    const int tid = threadIdx.x;
    const int m0 = blockIdx.y * 128;
    const int n0 = blockIdx.x * 128;
    const int tm = (tid / 16) * 8;
    const int tn = (tid % 16) * 8;
    const int lr = tid >> 1;
    const int lc = (tid & 1) * 4;

    const float* Aptr = A + (size_t)(m0 + lr) * K + lc;
    const float* Bptr = Bm + (size_t)(n0 + lr) * K + lc;

    float acc[8][8];
#pragma unroll
    for (int i = 0; i < 8; ++i)
#pragma unroll
        for (int j = 0; j < 8; ++j) acc[i][j] = 0.f;

    for (int kk = 0; kk < K; kk += 8) {
        float4 av = *(const float4*)(Aptr + kk);
        float4 bv = *(const float4*)(Bptr + kk);
        __syncthreads();
        As[lc + 0][lr] = av.x; As[lc + 1][lr] = av.y;
        As[lc + 2][lr] = av.z; As[lc + 3][lr] = av.w;
        Bs[lc + 0][lr] = bv.x; Bs[lc + 1][lr] = bv.y;
        Bs[lc + 2][lr] = bv.z; Bs[lc + 3][lr] = bv.w;
        __syncthreads();
#pragma unroll
        for (int k = 0; k < 8; ++k) {
            float ar[8], br[8];
            *(float4*)(ar)     = *(const float4*)&As[k][tm];
            *(float4*)(ar + 4) = *(const float4*)&As[k][tm + 4];
            *(float4*)(br)     = *(const float4*)&Bs[k][tn];
            *(float4*)(br + 4) = *(const float4*)&Bs[k][tn + 4];
#pragma unroll
            for (int i = 0; i < 8; ++i)
#pragma unroll
                for (int j = 0; j < 8; ++j)
                    acc[i][j] = fmaf(ar[i], br[j], acc[i][j]);
        }
    }
#pragma unroll
    for (int i = 0; i < 8; ++i) {
        float* cp = Cm + (size_t)(m0 + tm + i) * N + n0 + tn;
        *(float4*)(cp)     = make_float4(acc[i][0], acc[i][1], acc[i][2], acc[i][3]);
        *(float4*)(cp + 4) = make_float4(acc[i][4], acc[i][5], acc[i][6], acc[i][7]);
    }
}

// ---------------- persistent scan kernel ----------------
__global__ void __launch_bounds__(NTHR, 1) scan_kernel(
    const float* __restrict__ context,
    const float* __restrict__ init_h, const float* __restrict__ init_c,
    const float* __restrict__ x_mask, const float* __restrict__ y_mask,
    const float* __restrict__ U, const float* __restrict__ bvec,
    const float* __restrict__ Wx, const float* __restrict__ Ux,
    const float* __restrict__ bx, const float* __restrict__ b_att,
    const float* __restrict__ Wcomb, const float* __restrict__ Uatt,
    float* __restrict__ out)
{
    extern __shared__ float actS[];
    const int ltid = threadIdx.x;
    const int gtid = blockIdx.x * NTHR + ltid;
    const int nt = gridDim.x * NTHR;
    const int lane = ltid & 31;
    const int gwarp = gtid >> 5;
    const int nwarp = nt >> 5;

    float* out_hs = out;
    float* out_cs = out + TYN * BB * BH;
    float* out_atts = out + 2 * TYN * BB * BH;

    // init carry
    for (int i = gtid; i < BB * BH; i += nt) {
        g_hcur[i] = init_h[i];
        g_ccur[i] = init_c[i];
    }
    gbar();

    for (int t = 0; t < TYN; ++t) {
        // ---- stage h_cur -> smem [b][k] ----
        for (int i = ltid; i < BB * BH; i += NTHR)
            actS[(i >> 9) * SPAD + (i & 511)] = g_hcur[i];
        __syncthreads();

        // ---- P1: pre1_dot[b][g] = h_cur[b,:] . U[g,:] ----
        for (int pr = gwarp; pr < G4 / 2; pr += nwarp) {
            const int g0 = pr << 1;
            const float4* w0 = (const float4*)(U + (size_t)g0 * BH);
            const float4* w1 = (const float4*)(U + (size_t)(g0 + 1) * BH);
            const float4* ap = (const float4*)(actS + lane * SPAD);
            float a0 = 0.f, a1 = 0.f;
#pragma unroll 4
            for (int k = 0; k < BH / 4; ++k) {
                float4 a = ap[k], x0 = w0[k], x1 = w1[k];
                a0 = fmaf(a.x, x0.x, fmaf(a.y, x0.y, fmaf(a.z, x0.z, fmaf(a.w, x0.w, a0))));
                a1 = fmaf(a.x, x1.x, fmaf(a.y, x1.y, fmaf(a.z, x1.z, fmaf(a.w, x1.w, a1))));
            }
            g_pre1[lane * G4 + g0] = a0;
            g_pre1[lane * G4 + g0 + 1] = a1;
        }
        gbar();

        // ---- P1b: LSTM cell 1 ----
        {
            const float* xt = g_x + (size_t)t * (BB * G4);
            for (int i = gtid; i < BB * BH; i += nt) {
                const int b = i >> 9, h = i & 511;
                const int base = b * G4 + h;
                float pi = g_pre1[base]            + xt[base]            + bvec[h];
                float pf = g_pre1[base + BH]       + xt[base + BH]       + bvec[h + BH];
                float po = g_pre1[base + 2 * BH]   + xt[base + 2 * BH]   + bvec[h + 2 * BH];
                float pg = g_pre1[base + 3 * BH]   + xt[base + 3 * BH]   + bvec[h + 3 * BH];
                float c1 = sigf(pf) * g_ccur[i] + sigf(pi) * tanhf(pg);
                float h1 = sigf(po) * tanhf(c1);
                float ym = y_mask[t * BB + b];
                h1 = ym * h1 + (1.f - ym) * g_hcur[i];
                g_c1[i] = c1;
                g_h1[i] = h1;
            }
        }
        gbar();

        // ---- stage h1; P2: hproj[b][d] = h1[b,:] . Wcomb[d,:] + b_att[d] ----
        for (int i = ltid; i < BB * BH; i += NTHR)
            actS[(i >> 9) * SPAD + (i & 511)] = g_h1[i];
        __syncthreads();
        for (int pr = gwarp; pr < BC / 2; pr += nwarp) {
            const int d0 = pr << 1;
            const float4* w0 = (const float4*)(Wcomb + (size_t)d0 * BH);
            const float4* w1 = (const float4*)(Wcomb + (size_t)(d0 + 1) * BH);
            const float4* ap = (const float4*)(actS + lane * SPAD);
            float a0 = 0.f, a1 = 0.f;
#pragma unroll 4
            for (int k = 0; k < BH / 4; ++k) {
                float4 a = ap[k], x0 = w0[k], x1 = w1[k];
                a0 = fmaf(a.x, x0.x, fmaf(a.y, x0.y, fmaf(a.z, x0.z, fmaf(a.w, x0.w, a0))));
                a1 = fmaf(a.x, x1.x, fmaf(a.y, x1.y, fmaf(a.z, x1.z, fmaf(a.w, x1.w, a1))));
            }
            g_hproj[lane * BC + d0] = a0 + b_att[d0];
            g_hproj[lane * BC + d0 + 1] = a1 + b_att[d0 + 1];
        }
        gbar();

        // ---- P3: score[t',b] = xm * sum_c Uatt[c]*tanh(pctx[t',b,c]+hproj[b,c]) ----
        for (int it = gwarp; it < TXN * BB; it += nwarp) {
            const int b = it & 31;
            const float4* pc = (const float4*)(g_pctx + (size_t)it * BC);
            const float4* hp = (const float4*)(g_hproj + (size_t)b * BC);
            const float4* ua = (const float4*)(Uatt);
            float s = 0.f;
            for (int j = lane; j < BC / 4; j += 32) {
                float4 p = pc[j], hh = hp[j], u = ua[j];
                s += u.x * tanhf(p.x + hh.x);
                s += u.y * tanhf(p.y + hh.y);
                s += u.z * tanhf(p.z + hh.z);
                s += u.w * tanhf(p.w + hh.w);
            }
#pragma unroll
            for (int o = 16; o; o >>= 1) s += __shfl_xor_sync(0xffffffffu, s, o);
            if (lane == 0) g_score[it] = s * x_mask[it];
        }
        gbar();

        // ---- P4: softmax over t' + atted[b][c] (and write atts output) ----
        for (int i = gtid; i < BB * BC; i += nt) {
            const int b = i >> 10, c = i & 1023;
            float mx = -1e30f;
#pragma unroll 4
            for (int tp = 0; tp < TXN; ++tp) mx = fmaxf(mx, g_score[tp * BB + b]);
            float den = 0.f, acc = 0.f;
#pragma unroll 2
            for (int tp = 0; tp < TXN; ++tp) {
                float w = __expf(g_score[tp * BB + b] - mx) * x_mask[tp * BB + b];
                den += w;
                acc = fmaf(w, context[(size_t)(tp * BB + b) * BC + c], acc);
            }
            const float av = acc / den;
            g_atted[i] = av;
            out_atts[(size_t)t * (BB * BC) + i] = av;
        }
        gbar();

        // ---- stage [h1 | atted]; P5: pre2[b][g] = h1.Ux[g] + atted.Wx[g] + bx[g] ----
        for (int i = ltid; i < BB * BH; i += NTHR)
            actS[(i >> 9) * SPAD + (i & 511)] = g_h1[i];
        for (int i = ltid; i < BB * BC; i += NTHR)
            actS[(i >> 10) * SPAD + 512 + (i & 1023)] = g_atted[i];
        __syncthreads();
        for (int pr = gwarp; pr < G4 / 2; pr += nwarp) {
            const int g0 = pr << 1;
            float a0 = 0.f, a1 = 0.f;
            {
                const float4* w0 = (const float4*)(Ux + (size_t)g0 * BH);
                const float4* w1 = (const float4*)(Ux + (size_t)(g0 + 1) * BH);
                const float4* ap = (const float4*)(actS + lane * SPAD);
#pragma unroll 4
                for (int k = 0; k < BH / 4; ++k) {
                    float4 a = ap[k], x0 = w0[k], x1 = w1[k];
                    a0 = fmaf(a.x, x0.x, fmaf(a.y, x0.y, fmaf(a.z, x0.z, fmaf(a.w, x0.w, a0))));
                    a1 = fmaf(a.x, x1.x, fmaf(a.y, x1.y, fmaf(a.z, x1.z, fmaf(a.w, x1.w, a1))));
                }
            }
            {
                const float4* w0 = (const float4*)(Wx + (size_t)g0 * BC);
                const float4* w1 = (const float4*)(Wx + (size_t)(g0 + 1) * BC);
                const float4* ap = (const float4*)(actS + lane * SPAD + 512);
#pragma unroll 4
                for (int k = 0; k < BC / 4; ++k) {
                    float4 a = ap[k], x0 = w0[k], x1 = w1[k];
                    a0 = fmaf(a.x, x0.x, fmaf(a.y, x0.y, fmaf(a.z, x0.z, fmaf(a.w, x0.w, a0))));
                    a1 = fmaf(a.x, x1.x, fmaf(a.y, x1.y, fmaf(a.z, x1.z, fmaf(a.w, x1.w, a1))));
                }
            }
            g_pre2[lane * G4 + g0] = a0 + bx[g0];
            g_pre2[lane * G4 + g0 + 1] = a1 + bx[g0 + 1];
        }
        gbar();

        // ---- P5b: LSTM cell 2 + outputs + carry update ----
        for (int i = gtid; i < BB * BH; i += nt) {
            const int b = i >> 9, h = i & 511;
            const int base = b * G4 + h;
            float pi = g_pre2[base];
            float pf = g_pre2[base + BH];
            float po = g_pre2[base + 2 * BH];
            float pg = g_pre2[base + 3 * BH];
            float c2 = sigf(pf) * g_c1[i] + sigf(pi) * tanhf(pg);
            float h2 = sigf(po) * tanhf(c2);
            float ym = y_mask[t * BB + b];
            h2 = ym * h2 + (1.f - ym) * g_h1[i];
            g_hcur[i] = h2;
            g_ccur[i] = c2;
            out_hs[(size_t)t * (BB * BH) + i] = h2;
            out_cs[(size_t)t * (BB * BH) + i] = c2;
        }
        gbar();
    }
}

// ---------------- launch ----------------
extern "C" void kernel_launch(void* const* d_in, const int* in_sizes, int n_in,
                              void* d_out, int out_size) {
    const float* y_emb   = (const float*)d_in[0];   // [32,32,256]
    const float* context = (const float*)d_in[1];   // [128,32,1024]
    const float* init_h  = (const float*)d_in[2];   // [32,512]
    const float* init_c  = (const float*)d_in[3];
    const float* x_mask  = (const float*)d_in[4];   // [128,32,1]
    const float* y_mask  = (const float*)d_in[5];   // [32,32,1]
    const float* W       = (const float*)d_in[6];   // [2048,256]
    const float* U       = (const float*)d_in[7];   // [2048,512]
    const float* bvec    = (const float*)d_in[8];   // [2048]
    const float* Wx      = (const float*)d_in[9];   // [2048,1024]
    const float* Ux      = (const float*)d_in[10];  // [2048,512]
    const float* bx      = (const float*)d_in[11];  // [2048]
    const float* Wc_att  = (const float*)d_in[12];  // [1024,1024]
    const float* b_att   = (const float*)d_in[13];  // [1024]
    const float* Wcomb   = (const float*)d_in[14];  // [1024,512]
    const float* Uatt    = (const float*)d_in[15];  // [1,1024]

    cudaFuncSetAttribute(scan_kernel, cudaFuncAttributeMaxDynamicSharedMemorySize, SMEM_BYTES);

    // pctx[t*B+b][d] = context . Wc_att^T   (M=4096, N=1024, K=1024)
    {
        dim3 grid(1024 / 128, 4096 / 128);
        sgemm_nt<<<grid, 256>>>(0, context, Wc_att, 4096, 1024, 1024);
    }
    // x[t*B+b][g] = y_emb . W^T             (M=1024, N=2048, K=256)
    {
        dim3 grid(2048 / 128, 1024 / 128);
        sgemm_nt<<<grid, 256>>>(1, y_emb, W, 1024, 2048, 256);
    }

    scan_kernel<<<NBLK, NTHR, SMEM_BYTES>>>(context, init_h, init_c, x_mask, y_mask,
                                            U, bvec, Wx, Ux, bx, b_att, Wcomb, Uatt,
                                            (float*)d_out);
}

// round 2
// speedup vs baseline: 1.2797x; 1.2797x over previous
#include <cuda_runtime.h>
#include <math.h>

#define BI 256
#define BH 512
#define BC 1024
#define G4 2048
#define TYN 32
#define TXN 128
#define BB 32

#define NBLK 148
#define NTHR 512   // 16 warps

// ---------------- device scratch ----------------
__device__ float  g_pctx[(size_t)TXN * BB * BC];   // [t'*32+b][c] row-major
__device__ float  g_x[(size_t)TYN * BB * G4];      // [t*32+b][g] row-major
__device__ float4 g_hT4[128 * 32];                 // h[k4][b] packed k
__device__ float4 g_h1T4[128 * 32];
__device__ float4 g_attT4[256 * 32];               // atted[c4][b]
__device__ float  g_cT[BH * BB];                   // c[h][b]
__device__ float  g_c1T[BH * BB];
__device__ float  g_hproj[BB * BC];                // [b][d] row-major
__device__ float  g_score[TXN * BB];
__device__ unsigned g_count;                       // monotonic arrivals
__device__ unsigned g_flag;                        // monotonic release

__device__ __forceinline__ float sigf(float x) { return 1.f / (1.f + __expf(-x)); }
__device__ __forceinline__ float tanh_ap(float x) {
    float r; asm("tanh.approx.f32 %0, %1;" : "=f"(r) : "f"(x)); return r;
}
__device__ __forceinline__ unsigned ldacq(const unsigned* p) {
    unsigned v;
    asm volatile("ld.acquire.gpu.global.u32 %0, [%1];" : "=r"(v) : "l"(p) : "memory");
    return v;
}

// flag/acquire grid barrier: one RMW per block, read-only spin
__device__ __forceinline__ void gbar() {
    __syncthreads();
    if (threadIdx.x == 0) {
        __threadfence();
        unsigned a = atomicAdd(&g_count, 1u);
        unsigned target = (a / NBLK + 1u) * NBLK;
        if (a + 1u == target) {
            asm volatile("red.release.gpu.global.max.u32 [%0], %1;"
                         :: "l"(&g_flag), "r"(target) : "memory");
        } else {
            while (ldacq(&g_flag) < target) { }
        }
    }
    __syncthreads();
}

// ---------------- SGEMM (NT): C[m][n] = sum_k A[m*K+k]*Bm[n*K+k] ----------------
__global__ void __launch_bounds__(256) sgemm_nt(int sel,
                                                const float* __restrict__ A,
                                                const float* __restrict__ Bm,
                                                int M, int N, int K) {
    float* Cm = (sel == 0) ? g_pctx : g_x;
    __shared__ float As[8][128];
    __shared__ float Bs[8][128];
    const int tid = threadIdx.x;
    const int m0 = blockIdx.y * 128;
    const int n0 = blockIdx.x * 128;
    const int tm = (tid / 16) * 8;
    const int tn = (tid % 16) * 8;
    const int lr = tid >> 1;
    const int lc = (tid & 1) * 4;

    const float* Aptr = A + (size_t)(m0 + lr) * K + lc;
    const float* Bptr = Bm + (size_t)(n0 + lr) * K + lc;

    float acc[8][8];
#pragma unroll
    for (int i = 0; i < 8; ++i)
#pragma unroll
        for (int j = 0; j < 8; ++j) acc[i][j] = 0.f;

    for (int kk = 0; kk < K; kk += 8) {
        float4 av = *(const float4*)(Aptr + kk);
        float4 bv = *(const float4*)(Bptr + kk);
        __syncthreads();
        As[lc + 0][lr] = av.x; As[lc + 1][lr] = av.y;
        As[lc + 2][lr] = av.z; As[lc + 3][lr] = av.w;
        Bs[lc + 0][lr] = bv.x; Bs[lc + 1][lr] = bv.y;
        Bs[lc + 2][lr] = bv.z; Bs[lc + 3][lr] = bv.w;
        __syncthreads();
#pragma unroll
        for (int k = 0; k < 8; ++k) {
            float ar[8], br[8];
            *(float4*)(ar)     = *(const float4*)&As[k][tm];
            *(float4*)(ar + 4) = *(const float4*)&As[k][tm + 4];
            *(float4*)(br)     = *(const float4*)&Bs[k][tn];
            *(float4*)(br + 4) = *(const float4*)&Bs[k][tn + 4];
#pragma unroll
            for (int i = 0; i < 8; ++i)
#pragma unroll
                for (int j = 0; j < 8; ++j)
                    acc[i][j] = fmaf(ar[i], br[j], acc[i][j]);
        }
    }
#pragma unroll
    for (int i = 0; i < 8; ++i) {
        float* cp = Cm + (size_t)(m0 + tm + i) * N + n0 + tn;
        *(float4*)(cp)     = make_float4(acc[i][0], acc[i][1], acc[i][2], acc[i][3]);
        *(float4*)(cp + 4) = make_float4(acc[i][4], acc[i][5], acc[i][6], acc[i][7]);
    }
}

// ---------------- persistent scan kernel v2 ----------------
__global__ void __launch_bounds__(NTHR, 1) scan_kernel(
    const float* __restrict__ context,
    const float* __restrict__ init_h, const float* __restrict__ init_c,
    const float* __restrict__ x_mask, const float* __restrict__ y_mask,
    const float* __restrict__ U, const float* __restrict__ bvec,
    const float* __restrict__ Wx, const float* __restrict__ Ux,
    const float* __restrict__ bx, const float* __restrict__ b_att,
    const float* __restrict__ Wcomb, const float* __restrict__ Uatt,
    float* __restrict__ out)
{
    __shared__ float gateS[16 * 32];    // [warp][lane]

    const int ltid = threadIdx.x;
    const int w = ltid >> 5;
    const int lane = ltid & 31;
    const int beta = blockIdx.x;
    const int gtid = beta * NTHR + ltid;
    const int gw = beta * 16 + w;

    float* out_hs = out;
    float* out_cs = out + TYN * BB * BH;
    float* out_atts = out + 2 * TYN * BB * BH;

    float* hT = (float*)g_hT4;
    float* h1T = (float*)g_h1T4;
    float* attT = (float*)g_attT4;

    // ---- init: transpose init_h/init_c into hT4 / cT ----
    for (int i = gtid; i < BB * BH; i += NBLK * NTHR) {
        int k = i >> 5, b = i & 31;
        hT[(k >> 2) * 128 + b * 4 + (k & 3)] = init_h[b * BH + k];
        g_cT[k * 32 + b] = init_c[b * BH + k];
    }
    gbar();

    for (int t = 0; t < TYN; ++t) {
        // ================= P1: pre1 dot + LSTM cell 1 =================
        // blocks 0..127: block owns 4 h columns; warp = (h_local, gate)
        if (beta < 128) {
            const int h = (beta << 2) + (w >> 2);
            const int gate = w & 3;
            const float4* wrow = (const float4*)(U + (size_t)(gate * BH + h) * BH);
            float a0 = 0.f, a1 = 0.f, a2 = 0.f, a3 = 0.f;
#pragma unroll 8
            for (int k4 = 0; k4 < 128; ++k4) {
                float4 a = g_hT4[k4 * 32 + lane];
                float4 u = wrow[k4];
                a0 = fmaf(a.x, u.x, a0); a1 = fmaf(a.y, u.y, a1);
                a2 = fmaf(a.z, u.z, a2); a3 = fmaf(a.w, u.w, a3);
            }
            gateS[w * 32 + lane] = (a0 + a1) + (a2 + a3);
            __syncthreads();
            if (w < 4) {
                const int hh = (beta << 2) + w;
                const float* xt = g_x + (size_t)t * (BB * G4) + lane * G4;
                float pi = gateS[(w * 4 + 0) * 32 + lane] + xt[hh]           + bvec[hh];
                float pf = gateS[(w * 4 + 1) * 32 + lane] + xt[BH + hh]      + bvec[BH + hh];
                float po = gateS[(w * 4 + 2) * 32 + lane] + xt[2 * BH + hh]  + bvec[2 * BH + hh];
                float pg = gateS[(w * 4 + 3) * 32 + lane] + xt[3 * BH + hh]  + bvec[3 * BH + hh];
                float cold = g_cT[hh * 32 + lane];
                float hold = hT[(hh >> 2) * 128 + lane * 4 + (hh & 3)];
                float c1 = sigf(pf) * cold + sigf(pi) * tanhf(pg);
                float h1v = sigf(po) * tanhf(c1);
                float ym = y_mask[t * BB + lane];
                h1v = ym * h1v + (1.f - ym) * hold;
                g_c1T[hh * 32 + lane] = c1;
                h1T[(hh >> 2) * 128 + lane * 4 + (hh & 3)] = h1v;
            }
        }
        gbar();

        // ================= P2: hproj[b][d] = h1 . Wcomb[d] + b_att =================
        if (gw < BC) {
            const int d = gw;
            const float4* wrow = (const float4*)(Wcomb + (size_t)d * BH);
            float a0 = 0.f, a1 = 0.f, a2 = 0.f, a3 = 0.f;
#pragma unroll 8
            for (int k4 = 0; k4 < 128; ++k4) {
                float4 a = g_h1T4[k4 * 32 + lane];
                float4 u = wrow[k4];
                a0 = fmaf(a.x, u.x, a0); a1 = fmaf(a.y, u.y, a1);
                a2 = fmaf(a.z, u.z, a2); a3 = fmaf(a.w, u.w, a3);
            }
            g_hproj[lane * BC + d] = (a0 + a1) + (a2 + a3) + b_att[d];
        }
        gbar();

        // ================= P3: score[t'][b] =================
        for (int s = gw; s < TXN * BB; s += NBLK * 16) {
            const int b = s & 31;
            const float4* pc = (const float4*)(g_pctx + (size_t)s * BC);
            const float4* hp = (const float4*)(g_hproj + (size_t)b * BC);
            const float4* ua = (const float4*)(Uatt);
            float acc = 0.f;
#pragma unroll
            for (int j = 0; j < 8; ++j) {
                int idx = lane + j * 32;
                float4 p = pc[idx], hh = hp[idx], u = ua[idx];
                acc = fmaf(u.x, tanh_ap(p.x + hh.x), acc);
                acc = fmaf(u.y, tanh_ap(p.y + hh.y), acc);
                acc = fmaf(u.z, tanh_ap(p.z + hh.z), acc);
                acc = fmaf(u.w, tanh_ap(p.w + hh.w), acc);
            }
#pragma unroll
            for (int o = 16; o; o >>= 1) acc += __shfl_xor_sync(0xffffffffu, acc, o);
            if (lane == 0) g_score[s] = acc * x_mask[s];
        }
        gbar();

        // ================= P4: softmax over t' + atted =================
        if (gtid < BB * BC) {
            const int b = gtid >> 10, c = gtid & 1023;
            float mx = -1e30f;
#pragma unroll 4
            for (int tp = 0; tp < TXN; ++tp) mx = fmaxf(mx, g_score[tp * BB + b]);
            float den = 0.f, acc = 0.f;
#pragma unroll 2
            for (int tp = 0; tp < TXN; ++tp) {
                float wgt = __expf(g_score[tp * BB + b] - mx) * x_mask[tp * BB + b];
                den += wgt;
                acc = fmaf(wgt, context[(size_t)(tp * BB + b) * BC + c], acc);
            }
            const float av = acc / den;
            out_atts[(size_t)t * (BB * BC) + b * BC + c] = av;
            attT[(c >> 2) * 128 + b * 4 + (c & 3)] = av;
        }
        gbar();

        // ================= P5: pre2 dot + LSTM cell 2 + outputs =================
        if (beta < 128) {
            const int h = (beta << 2) + (w >> 2);
            const int gate = w & 3;
            float a0 = 0.f, a1 = 0.f, a2 = 0.f, a3 = 0.f;
            {
                const float4* wrow = (const float4*)(Ux + (size_t)(gate * BH + h) * BH);
#pragma unroll 8
                for (int k4 = 0; k4 < 128; ++k4) {
                    float4 a = g_h1T4[k4 * 32 + lane];
                    float4 u = wrow[k4];
                    a0 = fmaf(a.x, u.x, a0); a1 = fmaf(a.y, u.y, a1);
                    a2 = fmaf(a.z, u.z, a2); a3 = fmaf(a.w, u.w, a3);
                }
            }
            {
                const float4* wrow = (const float4*)(Wx + (size_t)(gate * BH + h) * BC);
#pragma unroll 8
                for (int k4 = 0; k4 < 256; ++k4) {
                    float4 a = g_attT4[k4 * 32 + lane];
                    float4 u = wrow[k4];
                    a0 = fmaf(a.x, u.x, a0); a1 = fmaf(a.y, u.y, a1);
                    a2 = fmaf(a.z, u.z, a2); a3 = fmaf(a.w, u.w, a3);
                }
            }
            gateS[w * 32 + lane] = (a0 + a1) + (a2 + a3);
            __syncthreads();
            if (w < 4) {
                const int hh = (beta << 2) + w;
                float pi = gateS[(w * 4 + 0) * 32 + lane] + bx[hh];
                float pf = gateS[(w * 4 + 1) * 32 + lane] + bx[BH + hh];
                float po = gateS[(w * 4 + 2) * 32 + lane] + bx[2 * BH + hh];
                float pg = gateS[(w * 4 + 3) * 32 + lane] + bx[3 * BH + hh];
                float c1 = g_c1T[hh * 32 + lane];
                float h1v = h1T[(hh >> 2) * 128 + lane * 4 + (hh & 3)];
                float c2 = sigf(pf) * c1 + sigf(pi) * tanhf(pg);
                float h2 = sigf(po) * tanhf(c2);
                float ym = y_mask[t * BB + lane];
                h2 = ym * h2 + (1.f - ym) * h1v;
                out_hs[(size_t)t * (BB * BH) + lane * BH + hh] = h2;
                out_cs[(size_t)t * (BB * BH) + lane * BH + hh] = c2;
                g_cT[hh * 32 + lane] = c2;
                hT[(hh >> 2) * 128 + lane * 4 + (hh & 3)] = h2;
            }
        }
        gbar();
    }
}

// ---------------- launch ----------------
extern "C" void kernel_launch(void* const* d_in, const int* in_sizes, int n_in,
                              void* d_out, int out_size) {
    const float* y_emb   = (const float*)d_in[0];
    const float* context = (const float*)d_in[1];
    const float* init_h  = (const float*)d_in[2];
    const float* init_c  = (const float*)d_in[3];
    const float* x_mask  = (const float*)d_in[4];
    const float* y_mask  = (const float*)d_in[5];
    const float* W       = (const float*)d_in[6];
    const float* U       = (const float*)d_in[7];
    const float* bvec    = (const float*)d_in[8];
    const float* Wx      = (const float*)d_in[9];
    const float* Ux      = (const float*)d_in[10];
    const float* bx      = (const float*)d_in[11];
    const float* Wc_att  = (const float*)d_in[12];
    const float* b_att   = (const float*)d_in[13];
    const float* Wcomb   = (const float*)d_in[14];
    const float* Uatt    = (const float*)d_in[15];

    {
        dim3 grid(1024 / 128, 4096 / 128);
        sgemm_nt<<<grid, 256>>>(0, context, Wc_att, 4096, 1024, 1024);
    }
    {
        dim3 grid(2048 / 128, 1024 / 128);
        sgemm_nt<<<grid, 256>>>(1, y_emb, W, 1024, 2048, 256);
    }

    scan_kernel<<<NBLK, NTHR>>>(context, init_h, init_c, x_mask, y_mask,
                                U, bvec, Wx, Ux, bx, b_att, Wcomb, Uatt,
                                (float*)d_out);
}

// round 3
// speedup vs baseline: 1.3614x; 1.0638x over previous
#include <cuda_runtime.h>
#include <math.h>

#define BI 256
#define BH 512
#define BC 1024
#define G4 2048
#define TYN 32
#define TXN 128
#define BB 32

#define NBLK 148
#define NTHR 512   // 16 warps

typedef unsigned long long u64t;

// ---------------- device scratch ----------------
__device__ float  g_pctx[(size_t)TXN * BB * BC];   // [t'*32+b][c]
__device__ float  g_xT[(size_t)TYN * G4 * BB];     // [t][g][b]
__device__ float4 g_hT4[128 * 32];                 // h carry [k4][b]
__device__ float4 g_act4[384 * 32];                // [h1 (k4<128) | atted (k4 128..384)] [k4][b]
__device__ float  g_cT[BH * BB];                   // c carry [h][b]
__device__ float  g_c1T[BH * BB];
__device__ float  g_hproj[BB * BC];                // [b][d]
__device__ float  g_score[TXN * BB];
__device__ unsigned g_cnt1[4];
__device__ unsigned g_cnt2;
__device__ unsigned g_flag;

__device__ __forceinline__ float sigf(float x) { return 1.f / (1.f + __expf(-x)); }
__device__ __forceinline__ float tanh_ap(float x) {
    float r; asm("tanh.approx.f32 %0, %1;" : "=f"(r) : "f"(x)); return r;
}
__device__ __forceinline__ u64t ffma2(u64t a, u64t b, u64t c) {
    u64t d; asm("fma.rn.f32x2 %0, %1, %2, %3;" : "=l"(d) : "l"(a), "l"(b), "l"(c));
    return d;
}
__device__ __forceinline__ float fsum2(u64t v) {
    float lo, hi; asm("mov.b64 {%0, %1}, %2;" : "=f"(lo), "=f"(hi) : "l"(v));
    return lo + hi;
}
__device__ __forceinline__ unsigned ldacq(const unsigned* p) {
    unsigned v;
    asm volatile("ld.acquire.gpu.global.u32 %0, [%1];" : "=r"(v) : "l"(p) : "memory");
    return v;
}

// two-level grid barrier: 4 sub-counters (37 each) + master, flag release
__device__ __forceinline__ void gbar(int beta) {
    __syncthreads();
    if (threadIdx.x == 0) {
        __threadfence();
        const int p = beta & 3;
        unsigned a = atomicAdd(&g_cnt1[p], 1u);
        unsigned epoch = a / 37u + 1u;
        if (a % 37u == 36u) {
            unsigned b = atomicAdd(&g_cnt2, 1u);
            if ((b & 3u) == 3u) {
                unsigned e = (b >> 2) + 1u;
                asm volatile("red.release.gpu.global.max.u32 [%0], %1;"
                             :: "l"(&g_flag), "r"(e) : "memory");
            }
        }
        while (ldacq(&g_flag) < epoch) { }
    }
    __syncthreads();
}

// ---------------- SGEMM (NT): C[m][n] = sum_k A[m*K+k]*Bm[n*K+k] ----------------
// sel==0 -> g_pctx row-major; sel==1 -> g_xT transposed epilogue [t][g][b]
__global__ void __launch_bounds__(256) sgemm_nt(int sel,
                                                const float* __restrict__ A,
                                                const float* __restrict__ Bm,
                                                int M, int N, int K) {
    __shared__ float As[8][128];
    __shared__ float Bs[8][128];
    const int tid = threadIdx.x;
    const int m0 = blockIdx.y * 128;
    const int n0 = blockIdx.x * 128;
    const int tm = (tid / 16) * 8;
    const int tn = (tid % 16) * 8;
    const int lr = tid >> 1;
    const int lc = (tid & 1) * 4;

    const float* Aptr = A + (size_t)(m0 + lr) * K + lc;
    const float* Bptr = Bm + (size_t)(n0 + lr) * K + lc;

    float acc[8][8];
#pragma unroll
    for (int i = 0; i < 8; ++i)
#pragma unroll
        for (int j = 0; j < 8; ++j) acc[i][j] = 0.f;

    for (int kk = 0; kk < K; kk += 8) {
        float4 av = *(const float4*)(Aptr + kk);
        float4 bv = *(const float4*)(Bptr + kk);
        __syncthreads();
        As[lc + 0][lr] = av.x; As[lc + 1][lr] = av.y;
        As[lc + 2][lr] = av.z; As[lc + 3][lr] = av.w;
        Bs[lc + 0][lr] = bv.x; Bs[lc + 1][lr] = bv.y;
        Bs[lc + 2][lr] = bv.z; Bs[lc + 3][lr] = bv.w;
        __syncthreads();
#pragma unroll
        for (int k = 0; k < 8; ++k) {
            float ar[8], br[8];
            *(float4*)(ar)     = *(const float4*)&As[k][tm];
            *(float4*)(ar + 4) = *(const float4*)&As[k][tm + 4];
            *(float4*)(br)     = *(const float4*)&Bs[k][tn];
            *(float4*)(br + 4) = *(const float4*)&Bs[k][tn + 4];
#pragma unroll
            for (int i = 0; i < 8; ++i)
#pragma unroll
                for (int j = 0; j < 8; ++j)
                    acc[i][j] = fmaf(ar[i], br[j], acc[i][j]);
        }
    }
    if (sel == 0) {
#pragma unroll
        for (int i = 0; i < 8; ++i) {
            float* cp = g_pctx + (size_t)(m0 + tm + i) * N + n0 + tn;
            *(float4*)(cp)     = make_float4(acc[i][0], acc[i][1], acc[i][2], acc[i][3]);
            *(float4*)(cp + 4) = make_float4(acc[i][4], acc[i][5], acc[i][6], acc[i][7]);
        }
    } else {
        // xT[t][g][b]: m = t*32+b, n = g
#pragma unroll
        for (int i = 0; i < 8; ++i) {
            const int m = m0 + tm + i;
            const int t = m >> 5, b = m & 31;
            float* base = g_xT + (size_t)t * (G4 * BB) + b;
#pragma unroll
            for (int j = 0; j < 8; ++j)
                base[(size_t)(n0 + tn + j) * BB] = acc[i][j];
        }
    }
}

// ---------------- persistent scan kernel v3 ----------------
__global__ void __launch_bounds__(NTHR, 1) scan_kernel(
    const float* __restrict__ context,
    const float* __restrict__ init_h, const float* __restrict__ init_c,
    const float* __restrict__ x_mask, const float* __restrict__ y_mask,
    const float* __restrict__ U, const float* __restrict__ bvec,
    const float* __restrict__ Wx, const float* __restrict__ Ux,
    const float* __restrict__ bx, const float* __restrict__ b_att,
    const float* __restrict__ Wcomb, const float* __restrict__ Uatt,
    float* __restrict__ out)
{
    __shared__ float partS[16 * 8 * 32];  // [lr][s][lane]  16KB
    __shared__ float gsumS[16 * 32];      // [lr][lane]

    const int ltid = threadIdx.x;
    const int w = ltid >> 5;
    const int lane = ltid & 31;
    const int beta = blockIdx.x;
    const int gtid = beta * NTHR + ltid;
    const int gw = beta * 16 + w;

    float* out_hs = out;
    float* out_cs = out + TYN * BB * BH;
    float* out_atts = out + 2 * TYN * BB * BH;

    float* hT = (float*)g_hT4;
    float* actF = (float*)g_act4;

    // init: transpose init_h/init_c
    for (int i = gtid; i < BB * BH; i += NBLK * NTHR) {
        int k = i >> 5, b = i & 31;
        hT[(k >> 2) * 128 + b * 4 + (k & 3)] = init_h[b * BH + k];
        g_cT[k * 32 + b] = init_c[b * BH + k];
    }
    gbar(beta);

    const int rg = w >> 3;        // row group 0/1
    const int sp = w & 7;         // k-split 0..7
    int rowoff1[8];               // row * BH for U / Ux
    int rowoffW[8];               // row * BC for Wx
#pragma unroll
    for (int r = 0; r < 8; ++r) {
        const int lr = rg * 8 + r;
        const int row = (lr >> 2) * BH + (beta << 2) + (lr & 3);
        rowoff1[r] = row * BH;
        rowoffW[r] = row * BC;
    }

    for (int t = 0; t < TYN; ++t) {
        // ================= P1: pre1 dot (block owns 4 h cols = 16 gate rows) ====
        if (beta < 128) {
            u64t acc0[8], acc1[8];
#pragma unroll
            for (int r = 0; r < 8; ++r) { acc0[r] = 0ull; acc1[r] = 0ull; }
            const ulonglong2* act = (const ulonglong2*)g_hT4;
            const ulonglong2* up[8];
#pragma unroll
            for (int r = 0; r < 8; ++r)
                up[r] = (const ulonglong2*)(U + rowoff1[r]) + sp * 16;
            const ulonglong2* ap = act + sp * 16 * 32 + lane;
#pragma unroll 8
            for (int k4 = 0; k4 < 16; ++k4) {
                ulonglong2 a = ap[k4 * 32];
#pragma unroll
                for (int r = 0; r < 8; ++r) {
                    ulonglong2 u = up[r][k4];
                    acc0[r] = ffma2(a.x, u.x, acc0[r]);
                    acc1[r] = ffma2(a.y, u.y, acc1[r]);
                }
            }
#pragma unroll
            for (int r = 0; r < 8; ++r)
                partS[(rg * 8 + r) * 256 + sp * 32 + lane] = fsum2(acc0[r]) + fsum2(acc1[r]);
        }
        __syncthreads();
        if (beta < 128) {
            float v = 0.f;
#pragma unroll
            for (int s8 = 0; s8 < 8; ++s8) v += partS[w * 256 + s8 * 32 + lane];
            gsumS[w * 32 + lane] = v;
        }
        __syncthreads();
        if (beta < 128 && w < 4) {
            const int hh = (beta << 2) + w;
            const float* xt = g_xT + (size_t)t * (G4 * BB);
            float pi = gsumS[(0 * 4 + w) * 32 + lane] + xt[(0 * BH + hh) * BB + lane] + bvec[hh];
            float pf = gsumS[(1 * 4 + w) * 32 + lane] + xt[(1 * BH + hh) * BB + lane] + bvec[BH + hh];
            float po = gsumS[(2 * 4 + w) * 32 + lane] + xt[(2 * BH + hh) * BB + lane] + bvec[2 * BH + hh];
            float pg = gsumS[(3 * 4 + w) * 32 + lane] + xt[(3 * BH + hh) * BB + lane] + bvec[3 * BH + hh];
            float cold = g_cT[hh * 32 + lane];
            float hold = hT[(hh >> 2) * 128 + lane * 4 + (hh & 3)];
            float c1 = sigf(pf) * cold + sigf(pi) * tanhf(pg);
            float h1v = sigf(po) * tanhf(c1);
            float ym = y_mask[t * BB + lane];
            h1v = ym * h1v + (1.f - ym) * hold;
            g_c1T[hh * 32 + lane] = c1;
            actF[(hh >> 2) * 128 + lane * 4 + (hh & 3)] = h1v;   // h1 region
        }
        gbar(beta);

        // ================= P2: hproj (warp owns 2 d rows, spread across blocks) ==
        {
            const int p = beta + 148 * w;
            if (p < 512) {
                const int d0 = p * 2;
                u64t a00 = 0, a01 = 0, a10 = 0, a11 = 0;
                const ulonglong2* act = (const ulonglong2*)g_act4;  // h1 region
                const ulonglong2* w0p = (const ulonglong2*)(Wcomb + (size_t)d0 * BH);
                const ulonglong2* w1p = (const ulonglong2*)(Wcomb + (size_t)(d0 + 1) * BH);
#pragma unroll 8
                for (int k4 = 0; k4 < 128; ++k4) {
                    ulonglong2 a = act[k4 * 32 + lane];
                    ulonglong2 u0 = w0p[k4];
                    ulonglong2 u1 = w1p[k4];
                    a00 = ffma2(a.x, u0.x, a00); a01 = ffma2(a.y, u0.y, a01);
                    a10 = ffma2(a.x, u1.x, a10); a11 = ffma2(a.y, u1.y, a11);
                }
                g_hproj[lane * BC + d0]     = fsum2(a00) + fsum2(a01) + b_att[d0];
                g_hproj[lane * BC + d0 + 1] = fsum2(a10) + fsum2(a11) + b_att[d0 + 1];
            }
        }
        gbar(beta);

        // ================= P3: score[t'][b] =================
        for (int s = gw; s < TXN * BB; s += NBLK * 16) {
            const int b = s & 31;
            const float4* pc = (const float4*)(g_pctx + (size_t)s * BC);
            const float4* hp = (const float4*)(g_hproj + (size_t)b * BC);
            const float4* ua = (const float4*)(Uatt);
            float acc = 0.f;
#pragma unroll
            for (int j = 0; j < 8; ++j) {
                int idx = lane + j * 32;
                float4 p = pc[idx], hh = hp[idx], u = ua[idx];
                acc = fmaf(u.x, tanh_ap(p.x + hh.x), acc);
                acc = fmaf(u.y, tanh_ap(p.y + hh.y), acc);
                acc = fmaf(u.z, tanh_ap(p.z + hh.z), acc);
                acc = fmaf(u.w, tanh_ap(p.w + hh.w), acc);
            }
#pragma unroll
            for (int o = 16; o; o >>= 1) acc += __shfl_xor_sync(0xffffffffu, acc, o);
            if (lane == 0) g_score[s] = acc * x_mask[s];
        }
        gbar(beta);

        // ================= P4: softmax + atted =================
        if (gtid < BB * BC) {
            const int b = gtid >> 10, c = gtid & 1023;
            float mx = -1e30f;
#pragma unroll 4
            for (int tp = 0; tp < TXN; ++tp) mx = fmaxf(mx, g_score[tp * BB + b]);
            float den = 0.f, acc = 0.f;
#pragma unroll 2
            for (int tp = 0; tp < TXN; ++tp) {
                float wgt = __expf(g_score[tp * BB + b] - mx) * x_mask[tp * BB + b];
                den += wgt;
                acc = fmaf(wgt, context[(size_t)(tp * BB + b) * BC + c], acc);
            }
            const float av = acc / den;
            out_atts[(size_t)t * (BB * BC) + b * BC + c] = av;
            actF[(128 + (c >> 2)) * 128 + b * 4 + (c & 3)] = av;  // atted region
        }
        gbar(beta);

        // ================= P5: pre2 dot + cell2 =================
        if (beta < 128) {
            u64t acc0[8], acc1[8];
#pragma unroll
            for (int r = 0; r < 8; ++r) { acc0[r] = 0ull; acc1[r] = 0ull; }
            // part A: Ux against h1 (k4 global [sp*16, sp*16+16))
            {
                const ulonglong2* up[8];
#pragma unroll
                for (int r = 0; r < 8; ++r)
                    up[r] = (const ulonglong2*)(Ux + rowoff1[r]) + sp * 16;
                const ulonglong2* ap = (const ulonglong2*)g_act4 + sp * 16 * 32 + lane;
#pragma unroll 8
                for (int k4 = 0; k4 < 16; ++k4) {
                    ulonglong2 a = ap[k4 * 32];
#pragma unroll
                    for (int r = 0; r < 8; ++r) {
                        ulonglong2 u = up[r][k4];
                        acc0[r] = ffma2(a.x, u.x, acc0[r]);
                        acc1[r] = ffma2(a.y, u.y, acc1[r]);
                    }
                }
            }
            // part B: Wx against atted (k4 global [128+sp*32, 128+sp*32+32))
            {
                const ulonglong2* up[8];
#pragma unroll
                for (int r = 0; r < 8; ++r)
                    up[r] = (const ulonglong2*)(Wx + rowoffW[r]) + sp * 32;
                const ulonglong2* ap = (const ulonglong2*)g_act4 + (128 + sp * 32) * 32 + lane;
#pragma unroll 8
                for (int k4 = 0; k4 < 32; ++k4) {
                    ulonglong2 a = ap[k4 * 32];
#pragma unroll
                    for (int r = 0; r < 8; ++r) {
                        ulonglong2 u = up[r][k4];
                        acc0[r] = ffma2(a.x, u.x, acc0[r]);
                        acc1[r] = ffma2(a.y, u.y, acc1[r]);
                    }
                }
            }
#pragma unroll
            for (int r = 0; r < 8; ++r)
                partS[(rg * 8 + r) * 256 + sp * 32 + lane] = fsum2(acc0[r]) + fsum2(acc1[r]);
        }
        __syncthreads();
        if (beta < 128) {
            float v = 0.f;
#pragma unroll
            for (int s8 = 0; s8 < 8; ++s8) v += partS[w * 256 + s8 * 32 + lane];
            gsumS[w * 32 + lane] = v;
        }
        __syncthreads();
        if (beta < 128 && w < 4) {
            const int hh = (beta << 2) + w;
            float pi = gsumS[(0 * 4 + w) * 32 + lane] + bx[hh];
            float pf = gsumS[(1 * 4 + w) * 32 + lane] + bx[BH + hh];
            float po = gsumS[(2 * 4 + w) * 32 + lane] + bx[2 * BH + hh];
            float pg = gsumS[(3 * 4 + w) * 32 + lane] + bx[3 * BH + hh];
            float c1 = g_c1T[hh * 32 + lane];
            float h1v = actF[(hh >> 2) * 128 + lane * 4 + (hh & 3)];
            float c2 = sigf(pf) * c1 + sigf(pi) * tanhf(pg);
            float h2 = sigf(po) * tanhf(c2);
            float ym = y_mask[t * BB + lane];
            h2 = ym * h2 + (1.f - ym) * h1v;
            out_hs[(size_t)t * (BB * BH) + lane * BH + hh] = h2;
            out_cs[(size_t)t * (BB * BH) + lane * BH + hh] = c2;
            g_cT[hh * 32 + lane] = c2;
            hT[(hh >> 2) * 128 + lane * 4 + (hh & 3)] = h2;
        }
        gbar(beta);
    }
}

// ---------------- launch ----------------
extern "C" void kernel_launch(void* const* d_in, const int* in_sizes, int n_in,
                              void* d_out, int out_size) {
    const float* y_emb   = (const float*)d_in[0];
    const float* context = (const float*)d_in[1];
    const float* init_h  = (const float*)d_in[2];
    const float* init_c  = (const float*)d_in[3];
    const float* x_mask  = (const float*)d_in[4];
    const float* y_mask  = (const float*)d_in[5];
    const float* W       = (const float*)d_in[6];
    const float* U       = (const float*)d_in[7];
    const float* bvec    = (const float*)d_in[8];
    const float* Wx      = (const float*)d_in[9];
    const float* Ux      = (const float*)d_in[10];
    const float* bx      = (const float*)d_in[11];
    const float* Wc_att  = (const float*)d_in[12];
    const float* b_att   = (const float*)d_in[13];
    const float* Wcomb   = (const float*)d_in[14];
    const float* Uatt    = (const float*)d_in[15];

    {
        dim3 grid(1024 / 128, 4096 / 128);
        sgemm_nt<<<grid, 256>>>(0, context, Wc_att, 4096, 1024, 1024);
    }
    {
        dim3 grid(2048 / 128, 1024 / 128);
        sgemm_nt<<<grid, 256>>>(1, y_emb, W, 1024, 2048, 256);
    }

    scan_kernel<<<NBLK, NTHR>>>(context, init_h, init_c, x_mask, y_mask,
                                U, bvec, Wx, Ux, bx, b_att, Wcomb, Uatt,
                                (float*)d_out);
}

// round 4
// speedup vs baseline: 1.8147x; 1.3329x over previous
#include <cuda_runtime.h>
#include <math.h>

#define BI 256
#define BH 512
#define BC 1024
#define G4 2048
#define TYN 32
#define TXN 128
#define BB 32

#define NBLK 148
#define NTHR 512   // 16 warps

typedef unsigned long long u64t;

// ---------------- device scratch ----------------
__device__ float  g_pctx[(size_t)TXN * BB * BC];   // [t'*32+b][c]
__device__ float  g_xT[(size_t)TYN * G4 * BB];     // [t][g][b]
__device__ float4 g_hT4[128 * 32];                 // h carry [k4][b]
__device__ float4 g_act4[384 * 32];                // [h1 | atted] [k4][b]
__device__ float  g_cT[BH * BB];                   // c carry [h][b]
__device__ float  g_c1T[BH * BB];
__device__ float  g_hproj[BB * BC];                // [b][d]
__device__ float  g_score[TXN * BB];
__device__ unsigned g_cnt1[4];
__device__ unsigned g_cnt2;
__device__ unsigned g_flag;

__device__ __forceinline__ float sigf(float x) { return 1.f / (1.f + __expf(-x)); }
__device__ __forceinline__ float tanh_ap(float x) {
    float r; asm("tanh.approx.f32 %0, %1;" : "=f"(r) : "f"(x)); return r;
}
__device__ __forceinline__ u64t ffma2(u64t a, u64t b, u64t c) {
    u64t d; asm("fma.rn.f32x2 %0, %1, %2, %3;" : "=l"(d) : "l"(a), "l"(b), "l"(c));
    return d;
}
__device__ __forceinline__ u64t pack2(float lo, float hi) {
    u64t v; asm("mov.b64 %0, {%1, %2};" : "=l"(v) : "f"(lo), "f"(hi));
    return v;
}
__device__ __forceinline__ float fsum2(u64t v) {
    float lo, hi; asm("mov.b64 {%0, %1}, %2;" : "=f"(lo), "=f"(hi) : "l"(v));
    return lo + hi;
}
__device__ __forceinline__ float flo2(u64t v) {
    float lo, hi; asm("mov.b64 {%0, %1}, %2;" : "=f"(lo), "=f"(hi) : "l"(v));
    return lo;
}
__device__ __forceinline__ float fhi2(u64t v) {
    float lo, hi; asm("mov.b64 {%0, %1}, %2;" : "=f"(lo), "=f"(hi) : "l"(v));
    return hi;
}
__device__ __forceinline__ unsigned ldacq(const unsigned* p) {
    unsigned v;
    asm volatile("ld.acquire.gpu.global.u32 %0, [%1];" : "=r"(v) : "l"(p) : "memory");
    return v;
}

// two-level grid barrier
__device__ __forceinline__ void gbar(int beta) {
    __syncthreads();
    if (threadIdx.x == 0) {
        __threadfence();
        const int p = beta & 3;
        unsigned a = atomicAdd(&g_cnt1[p], 1u);
        unsigned epoch = a / 37u + 1u;
        if (a % 37u == 36u) {
            unsigned b = atomicAdd(&g_cnt2, 1u);
            if ((b & 3u) == 3u) {
                unsigned e = (b >> 2) + 1u;
                asm volatile("red.release.gpu.global.max.u32 [%0], %1;"
                             :: "l"(&g_flag), "r"(e) : "memory");
            }
        }
        while (ldacq(&g_flag) < epoch) { }
    }
    __syncthreads();
}

// ---------------- fused SGEMM (NT), double-buffered, FFMA2 ----------------
// blocks 0..255: pctx = context(4096x1024) . Wc_att^T(1024x1024)
// blocks 256..383: xT = y_emb(1024x256) . W^T(2048x256), transposed epilogue
__global__ void __launch_bounds__(256) gemm_fused(const float* __restrict__ context,
                                                  const float* __restrict__ Wc_att,
                                                  const float* __restrict__ y_emb,
                                                  const float* __restrict__ W) {
    __shared__ __align__(16) float As[2][8][128];
    __shared__ __align__(16) float Bs[2][8][128];

    const int bid = blockIdx.x;
    const int job = (bid < 256) ? 0 : 1;
    const float* A;
    const float* Bm;
    int m0, n0, K, N;
    if (job == 0) {
        A = context; Bm = Wc_att; K = 1024; N = 1024;
        m0 = (bid >> 3) * 128; n0 = (bid & 7) * 128;
    } else {
        A = y_emb; Bm = W; K = 256; N = 2048;
        const int b2 = bid - 256;
        m0 = (b2 >> 4) * 128; n0 = (b2 & 15) * 128;
    }

    const int tid = threadIdx.x;
    const int tm = (tid / 16) * 8;
    const int tn = (tid % 16) * 8;
    const int lr = tid >> 1;
    const int lc = (tid & 1) * 4;

    const float* Aptr = A + (size_t)(m0 + lr) * K + lc;
    const float* Bptr = Bm + (size_t)(n0 + lr) * K + lc;

    u64t acc2[8][4];
#pragma unroll
    for (int i = 0; i < 8; ++i)
#pragma unroll
        for (int j = 0; j < 4; ++j) acc2[i][j] = 0ull;

    // preload tile 0
    {
        float4 av = *(const float4*)(Aptr);
        float4 bv = *(const float4*)(Bptr);
        As[0][lc + 0][lr] = av.x; As[0][lc + 1][lr] = av.y;
        As[0][lc + 2][lr] = av.z; As[0][lc + 3][lr] = av.w;
        Bs[0][lc + 0][lr] = bv.x; Bs[0][lc + 1][lr] = bv.y;
        Bs[0][lc + 2][lr] = bv.z; Bs[0][lc + 3][lr] = bv.w;
    }
    __syncthreads();

    const int T = K / 8;
    int cur = 0;
#pragma unroll 1
    for (int kk = 0; kk < T; ++kk) {
        float4 av, bv;
        const bool more = (kk + 1 < T);
        if (more) {
            av = *(const float4*)(Aptr + (kk + 1) * 8);
            bv = *(const float4*)(Bptr + (kk + 1) * 8);
        }
#pragma unroll
        for (int k = 0; k < 8; ++k) {
            float4 a0 = *(const float4*)&As[cur][k][tm];
            float4 a1 = *(const float4*)&As[cur][k][tm + 4];
            ulonglong2 bb0 = *(const ulonglong2*)&Bs[cur][k][tn];
            ulonglong2 bb1 = *(const ulonglong2*)&Bs[cur][k][tn + 4];
            float ar[8] = {a0.x, a0.y, a0.z, a0.w, a1.x, a1.y, a1.z, a1.w};
#pragma unroll
            for (int i = 0; i < 8; ++i) {
                u64t aa = pack2(ar[i], ar[i]);
                acc2[i][0] = ffma2(aa, bb0.x, acc2[i][0]);
                acc2[i][1] = ffma2(aa, bb0.y, acc2[i][1]);
                acc2[i][2] = ffma2(aa, bb1.x, acc2[i][2]);
                acc2[i][3] = ffma2(aa, bb1.y, acc2[i][3]);
            }
        }
        if (more) {
            const int nxt = cur ^ 1;
            As[nxt][lc + 0][lr] = av.x; As[nxt][lc + 1][lr] = av.y;
            As[nxt][lc + 2][lr] = av.z; As[nxt][lc + 3][lr] = av.w;
            Bs[nxt][lc + 0][lr] = bv.x; Bs[nxt][lc + 1][lr] = bv.y;
            Bs[nxt][lc + 2][lr] = bv.z; Bs[nxt][lc + 3][lr] = bv.w;
            __syncthreads();
            cur = nxt;
        }
    }

    if (job == 0) {
#pragma unroll
        for (int i = 0; i < 8; ++i) {
            float* cp = g_pctx + (size_t)(m0 + tm + i) * N + n0 + tn;
            *(float4*)(cp) = make_float4(flo2(acc2[i][0]), fhi2(acc2[i][0]),
                                         flo2(acc2[i][1]), fhi2(acc2[i][1]));
            *(float4*)(cp + 4) = make_float4(flo2(acc2[i][2]), fhi2(acc2[i][2]),
                                             flo2(acc2[i][3]), fhi2(acc2[i][3]));
        }
    } else {
#pragma unroll
        for (int i = 0; i < 8; ++i) {
            const int m = m0 + tm + i;
            const int t = m >> 5, b = m & 31;
            float* base = g_xT + (size_t)t * (G4 * BB) + b;
            float cv[8] = {flo2(acc2[i][0]), fhi2(acc2[i][0]),
                           flo2(acc2[i][1]), fhi2(acc2[i][1]),
                           flo2(acc2[i][2]), fhi2(acc2[i][2]),
                           flo2(acc2[i][3]), fhi2(acc2[i][3])};
#pragma unroll
            for (int j = 0; j < 8; ++j)
                base[(size_t)(n0 + tn + j) * BB] = cv[j];
        }
    }
}

// dot helper: 8 rows (2 gates x 4 hcol) against activation slice, low register pressure.
// base0/base1: ulonglong2 pointers to gate rows g0,g1 at column hcol=0, already offset to k-split.
// rowstride_u2: row stride in ulonglong2 units (K/4). nk4: iterations. actp: act slice (+lane).
template<int NK4>
__device__ __forceinline__ void dot8(const ulonglong2* __restrict__ actp,
                                     const ulonglong2* __restrict__ base0,
                                     const ulonglong2* __restrict__ base1,
                                     int rowstride_u2, u64t acc[8]) {
#pragma unroll 4
    for (int k = 0; k < NK4; ++k) {
        ulonglong2 a = actp[k * 32];
        {
            ulonglong2 w0 = base0[k];
            ulonglong2 w1 = base0[rowstride_u2 + k];
            ulonglong2 w2 = base0[2 * rowstride_u2 + k];
            ulonglong2 w3 = base0[3 * rowstride_u2 + k];
            acc[0] = ffma2(a.x, w0.x, acc[0]); acc[0] = ffma2(a.y, w0.y, acc[0]);
            acc[1] = ffma2(a.x, w1.x, acc[1]); acc[1] = ffma2(a.y, w1.y, acc[1]);
            acc[2] = ffma2(a.x, w2.x, acc[2]); acc[2] = ffma2(a.y, w2.y, acc[2]);
            acc[3] = ffma2(a.x, w3.x, acc[3]); acc[3] = ffma2(a.y, w3.y, acc[3]);
        }
        {
            ulonglong2 w0 = base1[k];
            ulonglong2 w1 = base1[rowstride_u2 + k];
            ulonglong2 w2 = base1[2 * rowstride_u2 + k];
            ulonglong2 w3 = base1[3 * rowstride_u2 + k];
            acc[4] = ffma2(a.x, w0.x, acc[4]); acc[4] = ffma2(a.y, w0.y, acc[4]);
            acc[5] = ffma2(a.x, w1.x, acc[5]); acc[5] = ffma2(a.y, w1.y, acc[5]);
            acc[6] = ffma2(a.x, w2.x, acc[6]); acc[6] = ffma2(a.y, w2.y, acc[6]);
            acc[7] = ffma2(a.x, w3.x, acc[7]); acc[7] = ffma2(a.y, w3.y, acc[7]);
        }
    }
}

// ---------------- persistent scan kernel v4 ----------------
__global__ void __launch_bounds__(NTHR, 1) scan_kernel(
    const float* __restrict__ context,
    const float* __restrict__ init_h, const float* __restrict__ init_c,
    const float* __restrict__ x_mask, const float* __restrict__ y_mask,
    const float* __restrict__ U, const float* __restrict__ bvec,
    const float* __restrict__ Wx, const float* __restrict__ Ux,
    const float* __restrict__ bx, const float* __restrict__ b_att,
    const float* __restrict__ Wcomb, const float* __restrict__ Uatt,
    float* __restrict__ out)
{
    __shared__ float partS[16 * 8 * 32];  // 16KB, reused as wS[32][128] in P4
    __shared__ float gsumS[16 * 32];

    const int ltid = threadIdx.x;
    const int w = ltid >> 5;
    const int lane = ltid & 31;
    const int beta = blockIdx.x;
    const int gtid = beta * NTHR + ltid;

    float* out_hs = out;
    float* out_cs = out + TYN * BB * BH;
    float* out_atts = out + 2 * TYN * BB * BH;

    float* hT = (float*)g_hT4;
    float* actF = (float*)g_act4;
    float* wS = partS;  // [b][tp] 32x128

    // init carry (transposed)
    for (int i = gtid; i < BB * BH; i += NBLK * NTHR) {
        int k = i >> 5, b = i & 31;
        hT[(k >> 2) * 128 + b * 4 + (k & 3)] = init_h[b * BH + k];
        g_cT[k * 32 + b] = init_c[b * BH + k];
    }
    gbar(beta);

    const int rg = w >> 3;        // row group (gates 2rg, 2rg+1)
    const int sp = w & 7;         // k-split

    for (int t = 0; t < TYN; ++t) {
        // ================= P1: pre1 = hT . U rows =================
        if (beta < 128) {
            u64t acc[8];
#pragma unroll
            for (int r = 0; r < 8; ++r) acc[r] = 0ull;
            const ulonglong2* actp = (const ulonglong2*)g_hT4 + sp * 16 * 32 + lane;
            const ulonglong2* b0 = (const ulonglong2*)(U + ((size_t)(rg * 2 + 0) * BH + (beta << 2)) * BH) + sp * 16;
            const ulonglong2* b1 = (const ulonglong2*)(U + ((size_t)(rg * 2 + 1) * BH + (beta << 2)) * BH) + sp * 16;
            dot8<16>(actp, b0, b1, BH / 4, acc);
#pragma unroll
            for (int r = 0; r < 8; ++r) {
                const int ri = (rg * 2 + (r >> 2)) * 4 + (r & 3);
                partS[ri * 256 + sp * 32 + lane] = fsum2(acc[r]);
            }
        }
        __syncthreads();
        if (beta < 128) {
            float v = 0.f;
#pragma unroll
            for (int s8 = 0; s8 < 8; ++s8) v += partS[w * 256 + s8 * 32 + lane];
            gsumS[w * 32 + lane] = v;
        }
        __syncthreads();
        if (beta < 128 && w < 4) {
            const int hh = (beta << 2) + w;
            const float* xt = g_xT + (size_t)t * (G4 * BB);
            float pi = gsumS[(0 * 4 + w) * 32 + lane] + xt[(0 * BH + hh) * BB + lane] + bvec[hh];
            float pf = gsumS[(1 * 4 + w) * 32 + lane] + xt[(1 * BH + hh) * BB + lane] + bvec[BH + hh];
            float po = gsumS[(2 * 4 + w) * 32 + lane] + xt[(2 * BH + hh) * BB + lane] + bvec[2 * BH + hh];
            float pg = gsumS[(3 * 4 + w) * 32 + lane] + xt[(3 * BH + hh) * BB + lane] + bvec[3 * BH + hh];
            float cold = g_cT[hh * 32 + lane];
            float hold = hT[(hh >> 2) * 128 + lane * 4 + (hh & 3)];
            float c1 = sigf(pf) * cold + sigf(pi) * tanhf(pg);
            float h1v = sigf(po) * tanhf(c1);
            float ym = y_mask[t * BB + lane];
            h1v = ym * h1v + (1.f - ym) * hold;
            g_c1T[hh * 32 + lane] = c1;
            actF[(hh >> 2) * 128 + lane * 4 + (hh & 3)] = h1v;
        }
        gbar(beta);

        // ================= P2: hproj =================
        {
            const int p = beta + 148 * w;
            if (p < 512) {
                const int d0 = p * 2;
                u64t a00 = 0, a01 = 0, a10 = 0, a11 = 0;
                const ulonglong2* act = (const ulonglong2*)g_act4;
                const ulonglong2* w0p = (const ulonglong2*)(Wcomb + (size_t)d0 * BH);
                const ulonglong2* w1p = (const ulonglong2*)(Wcomb + (size_t)(d0 + 1) * BH);
#pragma unroll 4
                for (int k4 = 0; k4 < 128; ++k4) {
                    ulonglong2 a = act[k4 * 32 + lane];
                    ulonglong2 u0 = w0p[k4];
                    ulonglong2 u1 = w1p[k4];
                    a00 = ffma2(a.x, u0.x, a00); a01 = ffma2(a.y, u0.y, a01);
                    a10 = ffma2(a.x, u1.x, a10); a11 = ffma2(a.y, u1.y, a11);
                }
                g_hproj[lane * BC + d0]     = fsum2(a00) + fsum2(a01) + b_att[d0];
                g_hproj[lane * BC + d0 + 1] = fsum2(a10) + fsum2(a11) + b_att[d0 + 1];
            }
        }
        gbar(beta);

        // ================= P3: score =================
        for (int s = w * 148 + beta; s < TXN * BB; s += NBLK * 16) {
            const int b = s & 31;
            const float4* pc = (const float4*)(g_pctx + (size_t)s * BC);
            const float4* hp = (const float4*)(g_hproj + (size_t)b * BC);
            const float4* ua = (const float4*)(Uatt);
            float acc = 0.f;
#pragma unroll
            for (int j = 0; j < 8; ++j) {
                int idx = lane + j * 32;
                float4 p = pc[idx], hh = hp[idx], u = ua[idx];
                acc = fmaf(u.x, tanh_ap(p.x + hh.x), acc);
                acc = fmaf(u.y, tanh_ap(p.y + hh.y), acc);
                acc = fmaf(u.z, tanh_ap(p.z + hh.z), acc);
                acc = fmaf(u.w, tanh_ap(p.w + hh.w), acc);
            }
#pragma unroll
            for (int o = 16; o; o >>= 1) acc += __shfl_xor_sync(0xffffffffu, acc, o);
            if (lane == 0) g_score[s] = acc * x_mask[s];
        }
        gbar(beta);

        // ================= P4a: softmax weights (block-local, all b) =========
        {
#pragma unroll
            for (int q = 0; q < 2; ++q) {
                const int b = w * 2 + q;
                float s0 = g_score[(lane +  0) * BB + b];
                float s1 = g_score[(lane + 32) * BB + b];
                float s2 = g_score[(lane + 64) * BB + b];
                float s3 = g_score[(lane + 96) * BB + b];
                float mx = fmaxf(fmaxf(s0, s1), fmaxf(s2, s3));
#pragma unroll
                for (int o = 16; o; o >>= 1) mx = fmaxf(mx, __shfl_xor_sync(0xffffffffu, mx, o));
                float e0 = __expf(s0 - mx) * x_mask[(lane +  0) * BB + b];
                float e1 = __expf(s1 - mx) * x_mask[(lane + 32) * BB + b];
                float e2 = __expf(s2 - mx) * x_mask[(lane + 64) * BB + b];
                float e3 = __expf(s3 - mx) * x_mask[(lane + 96) * BB + b];
                float sm = (e0 + e1) + (e2 + e3);
#pragma unroll
                for (int o = 16; o; o >>= 1) sm += __shfl_xor_sync(0xffffffffu, sm, o);
                const float inv = 1.f / sm;
                wS[b * 128 + lane +  0] = e0 * inv;
                wS[b * 128 + lane + 32] = e1 * inv;
                wS[b * 128 + lane + 64] = e2 * inv;
                wS[b * 128 + lane + 96] = e3 * inv;
            }
        }
        __syncthreads();

        // ================= P4b: atted[b][c] =================
        {
            const int task = w * 148 + beta;   // 1024 tasks: (b, 32-c chunk)
            if (task < 1024) {
                const int b = task >> 5;
                const int c = (task & 31) * 32 + lane;
                const float* ctxp = context + (size_t)b * BC + c;
                const float* wp = wS + b * 128;
                float a0 = 0.f, a1 = 0.f, a2 = 0.f, a3 = 0.f;
#pragma unroll 8
                for (int tp = 0; tp < TXN; tp += 4) {
                    a0 = fmaf(wp[tp + 0], ctxp[(size_t)(tp + 0) * (BB * BC)], a0);
                    a1 = fmaf(wp[tp + 1], ctxp[(size_t)(tp + 1) * (BB * BC)], a1);
                    a2 = fmaf(wp[tp + 2], ctxp[(size_t)(tp + 2) * (BB * BC)], a2);
                    a3 = fmaf(wp[tp + 3], ctxp[(size_t)(tp + 3) * (BB * BC)], a3);
                }
                const float av = (a0 + a1) + (a2 + a3);
                out_atts[(size_t)t * (BB * BC) + b * BC + c] = av;
                actF[(128 + (c >> 2)) * 128 + b * 4 + (c & 3)] = av;
            }
        }
        gbar(beta);

        // ================= P5: pre2 = h1.Ux + atted.Wx =================
        if (beta < 128) {
            u64t acc[8];
#pragma unroll
            for (int r = 0; r < 8; ++r) acc[r] = 0ull;
            {
                const ulonglong2* actp = (const ulonglong2*)g_act4 + sp * 16 * 32 + lane;
                const ulonglong2* b0 = (const ulonglong2*)(Ux + ((size_t)(rg * 2 + 0) * BH + (beta << 2)) * BH) + sp * 16;
                const ulonglong2* b1 = (const ulonglong2*)(Ux + ((size_t)(rg * 2 + 1) * BH + (beta << 2)) * BH) + sp * 16;
                dot8<16>(actp, b0, b1, BH / 4, acc);
            }
            {
                const ulonglong2* actp = (const ulonglong2*)g_act4 + (128 + sp * 32) * 32 + lane;
                const ulonglong2* b0 = (const ulonglong2*)(Wx + ((size_t)(rg * 2 + 0) * BH + (beta << 2)) * BC) + sp * 32;
                const ulonglong2* b1 = (const ulonglong2*)(Wx + ((size_t)(rg * 2 + 1) * BH + (beta << 2)) * BC) + sp * 32;
                dot8<32>(actp, b0, b1, BC / 4, acc);
            }
#pragma unroll
            for (int r = 0; r < 8; ++r) {
                const int ri = (rg * 2 + (r >> 2)) * 4 + (r & 3);
                partS[ri * 256 + sp * 32 + lane] = fsum2(acc[r]);
            }
        }
        __syncthreads();
        if (beta < 128) {
            float v = 0.f;
#pragma unroll
            for (int s8 = 0; s8 < 8; ++s8) v += partS[w * 256 + s8 * 32 + lane];
            gsumS[w * 32 + lane] = v;
        }
        __syncthreads();
        if (beta < 128 && w < 4) {
            const int hh = (beta << 2) + w;
            float pi = gsumS[(0 * 4 + w) * 32 + lane] + bx[hh];
            float pf = gsumS[(1 * 4 + w) * 32 + lane] + bx[BH + hh];
            float po = gsumS[(2 * 4 + w) * 32 + lane] + bx[2 * BH + hh];
            float pg = gsumS[(3 * 4 + w) * 32 + lane] + bx[3 * BH + hh];
            float c1 = g_c1T[hh * 32 + lane];
            float h1v = actF[(hh >> 2) * 128 + lane * 4 + (hh & 3)];
            float c2 = sigf(pf) * c1 + sigf(pi) * tanhf(pg);
            float h2 = sigf(po) * tanhf(c2);
            float ym = y_mask[t * BB + lane];
            h2 = ym * h2 + (1.f - ym) * h1v;
            out_hs[(size_t)t * (BB * BH) + lane * BH + hh] = h2;
            out_cs[(size_t)t * (BB * BH) + lane * BH + hh] = c2;
            g_cT[hh * 32 + lane] = c2;
            hT[(hh >> 2) * 128 + lane * 4 + (hh & 3)] = h2;
        }
        gbar(beta);
    }
}

// ---------------- launch ----------------
extern "C" void kernel_launch(void* const* d_in, const int* in_sizes, int n_in,
                              void* d_out, int out_size) {
    const float* y_emb   = (const float*)d_in[0];
    const float* context = (const float*)d_in[1];
    const float* init_h  = (const float*)d_in[2];
    const float* init_c  = (const float*)d_in[3];
    const float* x_mask  = (const float*)d_in[4];
    const float* y_mask  = (const float*)d_in[5];
    const float* W       = (const float*)d_in[6];
    const float* U       = (const float*)d_in[7];
    const float* bvec    = (const float*)d_in[8];
    const float* Wx      = (const float*)d_in[9];
    const float* Ux      = (const float*)d_in[10];
    const float* bx      = (const float*)d_in[11];
    const float* Wc_att  = (const float*)d_in[12];
    const float* b_att   = (const float*)d_in[13];
    const float* Wcomb   = (const float*)d_in[14];
    const float* Uatt    = (const float*)d_in[15];

    gemm_fused<<<384, 256>>>(context, Wc_att, y_emb, W);

    scan_kernel<<<NBLK, NTHR>>>(context, init_h, init_c, x_mask, y_mask,
                                U, bvec, Wx, Ux, bx, b_att, Wcomb, Uatt,
                                (float*)d_out);
}

// round 5
// speedup vs baseline: 1.8149x; 1.0001x over previous
#include <cuda_runtime.h>
#include <math.h>

#define BI 256
#define BH 512
#define BC 1024
#define G4 2048
#define TYN 32
#define TXN 128
#define BB 32

#define NBLK 148
#define NTHR 512   // 16 warps

typedef unsigned long long u64t;

// ---------------- device scratch ----------------
__device__ float  g_pctx[(size_t)TXN * BB * BC];   // [t'*32+b][c]
__device__ float  g_xT[(size_t)TYN * G4 * BB];     // [t][g][b]
__device__ float4 g_hT4[128 * 32];                 // h carry [k4][b]
__device__ float4 g_act4[384 * 32];                // [h1 | atted] [k4][b]
__device__ float  g_cT[BH * BB];                   // c carry [h][b]
__device__ float  g_c1T[BH * BB];
__device__ float  g_hproj[BB * BC];                // [b][d]
__device__ float  g_score[TXN * BB];
__device__ unsigned g_cnt1[4];
__device__ unsigned g_cnt2;
__device__ unsigned g_flag;

__device__ __forceinline__ float sigf(float x) { return 1.f / (1.f + __expf(-x)); }
__device__ __forceinline__ float tanh_ap(float x) {
    float r; asm("tanh.approx.f32 %0, %1;" : "=f"(r) : "f"(x)); return r;
}
__device__ __forceinline__ u64t ffma2(u64t a, u64t b, u64t c) {
    u64t d; asm("fma.rn.f32x2 %0, %1, %2, %3;" : "=l"(d) : "l"(a), "l"(b), "l"(c));
    return d;
}
__device__ __forceinline__ u64t pack2(float lo, float hi) {
    u64t v; asm("mov.b64 %0, {%1, %2};" : "=l"(v) : "f"(lo), "f"(hi));
    return v;
}
__device__ __forceinline__ float fsum2(u64t v) {
    float lo, hi; asm("mov.b64 {%0, %1}, %2;" : "=f"(lo), "=f"(hi) : "l"(v));
    return lo + hi;
}
__device__ __forceinline__ float flo2(u64t v) {
    float lo, hi; asm("mov.b64 {%0, %1}, %2;" : "=f"(lo), "=f"(hi) : "l"(v));
    return lo;
}
__device__ __forceinline__ float fhi2(u64t v) {
    float lo, hi; asm("mov.b64 {%0, %1}, %2;" : "=f"(lo), "=f"(hi) : "l"(v));
    return hi;
}
__device__ __forceinline__ unsigned ldacq(const unsigned* p) {
    unsigned v;
    asm volatile("ld.acquire.gpu.global.u32 %0, [%1];" : "=r"(v) : "l"(p) : "memory");
    return v;
}

// two-level grid barrier
__device__ __forceinline__ void gbar(int beta) {
    __syncthreads();
    if (threadIdx.x == 0) {
        __threadfence();
        const int p = beta & 3;
        unsigned a = atomicAdd(&g_cnt1[p], 1u);
        unsigned epoch = a / 37u + 1u;
        if (a % 37u == 36u) {
            unsigned b = atomicAdd(&g_cnt2, 1u);
            if ((b & 3u) == 3u) {
                unsigned e = (b >> 2) + 1u;
                asm volatile("red.release.gpu.global.max.u32 [%0], %1;"
                             :: "l"(&g_flag), "r"(e) : "memory");
            }
        }
        while (ldacq(&g_flag) < epoch) { }
    }
    __syncthreads();
}

// ---------------- fused SGEMM (NT), double-buffered, FFMA2 ----------------
// blocks 0..255: pctx = context(4096x1024) . Wc_att^T(1024x1024)
// blocks 256..383: xT = y_emb(1024x256) . W^T(2048x256), transposed epilogue
__global__ void __launch_bounds__(256) gemm_fused(const float* __restrict__ context,
                                                  const float* __restrict__ Wc_att,
                                                  const float* __restrict__ y_emb,
                                                  const float* __restrict__ W) {
    __shared__ __align__(16) float As[2][8][128];
    __shared__ __align__(16) float Bs[2][8][128];

    const int bid = blockIdx.x;
    const int job = (bid < 256) ? 0 : 1;
    const float* A;
    const float* Bm;
    int m0, n0, K, N;
    if (job == 0) {
        A = context; Bm = Wc_att; K = 1024; N = 1024;
        m0 = (bid >> 3) * 128; n0 = (bid & 7) * 128;
    } else {
        A = y_emb; Bm = W; K = 256; N = 2048;
        const int b2 = bid - 256;
        m0 = (b2 >> 4) * 128; n0 = (b2 & 15) * 128;
    }

    const int tid = threadIdx.x;
    const int tm = (tid / 16) * 8;
    const int tn = (tid % 16) * 8;
    const int lr = tid >> 1;
    const int lc = (tid & 1) * 4;

    const float* Aptr = A + (size_t)(m0 + lr) * K + lc;
    const float* Bptr = Bm + (size_t)(n0 + lr) * K + lc;

    u64t acc2[8][4];
#pragma unroll
    for (int i = 0; i < 8; ++i)
#pragma unroll
        for (int j = 0; j < 4; ++j) acc2[i][j] = 0ull;

    // preload tile 0
    {
        float4 av = *(const float4*)(Aptr);
        float4 bv = *(const float4*)(Bptr);
        As[0][lc + 0][lr] = av.x; As[0][lc + 1][lr] = av.y;
        As[0][lc + 2][lr] = av.z; As[0][lc + 3][lr] = av.w;
        Bs[0][lc + 0][lr] = bv.x; Bs[0][lc + 1][lr] = bv.y;
        Bs[0][lc + 2][lr] = bv.z; Bs[0][lc + 3][lr] = bv.w;
    }
    __syncthreads();

    const int T = K / 8;
    int cur = 0;
#pragma unroll 1
    for (int kk = 0; kk < T; ++kk) {
        float4 av, bv;
        const bool more = (kk + 1 < T);
        if (more) {
            av = *(const float4*)(Aptr + (kk + 1) * 8);
            bv = *(const float4*)(Bptr + (kk + 1) * 8);
        }
#pragma unroll
        for (int k = 0; k < 8; ++k) {
            float4 a0 = *(const float4*)&As[cur][k][tm];
            float4 a1 = *(const float4*)&As[cur][k][tm + 4];
            ulonglong2 bb0 = *(const ulonglong2*)&Bs[cur][k][tn];
            ulonglong2 bb1 = *(const ulonglong2*)&Bs[cur][k][tn + 4];
            float ar[8] = {a0.x, a0.y, a0.z, a0.w, a1.x, a1.y, a1.z, a1.w};
#pragma unroll
            for (int i = 0; i < 8; ++i) {
                u64t aa = pack2(ar[i], ar[i]);
                acc2[i][0] = ffma2(aa, bb0.x, acc2[i][0]);
                acc2[i][1] = ffma2(aa, bb0.y, acc2[i][1]);
                acc2[i][2] = ffma2(aa, bb1.x, acc2[i][2]);
                acc2[i][3] = ffma2(aa, bb1.y, acc2[i][3]);
            }
        }
        if (more) {
            const int nxt = cur ^ 1;
            As[nxt][lc + 0][lr] = av.x; As[nxt][lc + 1][lr] = av.y;
            As[nxt][lc + 2][lr] = av.z; As[nxt][lc + 3][lr] = av.w;
            Bs[nxt][lc + 0][lr] = bv.x; Bs[nxt][lc + 1][lr] = bv.y;
            Bs[nxt][lc + 2][lr] = bv.z; Bs[nxt][lc + 3][lr] = bv.w;
            __syncthreads();
            cur = nxt;
        }
    }

    if (job == 0) {
#pragma unroll
        for (int i = 0; i < 8; ++i) {
            float* cp = g_pctx + (size_t)(m0 + tm + i) * N + n0 + tn;
            *(float4*)(cp) = make_float4(flo2(acc2[i][0]), fhi2(acc2[i][0]),
                                         flo2(acc2[i][1]), fhi2(acc2[i][1]));
            *(float4*)(cp + 4) = make_float4(flo2(acc2[i][2]), fhi2(acc2[i][2]),
                                             flo2(acc2[i][3]), fhi2(acc2[i][3]));
        }
    } else {
#pragma unroll
        for (int i = 0; i < 8; ++i) {
            const int m = m0 + tm + i;
            const int t = m >> 5, b = m & 31;
            float* base = g_xT + (size_t)t * (G4 * BB) + b;
            float cv[8] = {flo2(acc2[i][0]), fhi2(acc2[i][0]),
                           flo2(acc2[i][1]), fhi2(acc2[i][1]),
                           flo2(acc2[i][2]), fhi2(acc2[i][2]),
                           flo2(acc2[i][3]), fhi2(acc2[i][3])};
#pragma unroll
            for (int j = 0; j < 8; ++j)
                base[(size_t)(n0 + tn + j) * BB] = cv[j];
        }
    }
}

// dot helper: 8 rows (2 gates x 4 hcol) against activation slice, low register pressure.
// base0/base1: ulonglong2 pointers to gate rows g0,g1 at column hcol=0, already offset to k-split.
// rowstride_u2: row stride in ulonglong2 units (K/4). nk4: iterations. actp: act slice (+lane).
template<int NK4>
__device__ __forceinline__ void dot8(const ulonglong2* __restrict__ actp,
                                     const ulonglong2* __restrict__ base0,
                                     const ulonglong2* __restrict__ base1,
                                     int rowstride_u2, u64t acc[8]) {
#pragma unroll 4
    for (int k = 0; k < NK4; ++k) {
        ulonglong2 a = actp[k * 32];
        {
            ulonglong2 w0 = base0[k];
            ulonglong2 w1 = base0[rowstride_u2 + k];
            ulonglong2 w2 = base0[2 * rowstride_u2 + k];
            ulonglong2 w3 = base0[3 * rowstride_u2 + k];
            acc[0] = ffma2(a.x, w0.x, acc[0]); acc[0] = ffma2(a.y, w0.y, acc[0]);
            acc[1] = ffma2(a.x, w1.x, acc[1]); acc[1] = ffma2(a.y, w1.y, acc[1]);
            acc[2] = ffma2(a.x, w2.x, acc[2]); acc[2] = ffma2(a.y, w2.y, acc[2]);
            acc[3] = ffma2(a.x, w3.x, acc[3]); acc[3] = ffma2(a.y, w3.y, acc[3]);
        }
        {
            ulonglong2 w0 = base1[k];
            ulonglong2 w1 = base1[rowstride_u2 + k];
            ulonglong2 w2 = base1[2 * rowstride_u2 + k];
            ulonglong2 w3 = base1[3 * rowstride_u2 + k];
            acc[4] = ffma2(a.x, w0.x, acc[4]); acc[4] = ffma2(a.y, w0.y, acc[4]);
            acc[5] = ffma2(a.x, w1.x, acc[5]); acc[5] = ffma2(a.y, w1.y, acc[5]);
            acc[6] = ffma2(a.x, w2.x, acc[6]); acc[6] = ffma2(a.y, w2.y, acc[6]);
            acc[7] = ffma2(a.x, w3.x, acc[7]); acc[7] = ffma2(a.y, w3.y, acc[7]);
        }
    }
}

// ---------------- persistent scan kernel v4 ----------------
__global__ void __launch_bounds__(NTHR, 1) scan_kernel(
    const float* __restrict__ context,
    const float* __restrict__ init_h, const float* __restrict__ init_c,
    const float* __restrict__ x_mask, const float* __restrict__ y_mask,
    const float* __restrict__ U, const float* __restrict__ bvec,
    const float* __restrict__ Wx, const float* __restrict__ Ux,
    const float* __restrict__ bx, const float* __restrict__ b_att,
    const float* __restrict__ Wcomb, const float* __restrict__ Uatt,
    float* __restrict__ out)
{
    __shared__ float partS[16 * 8 * 32];  // 16KB, reused as wS[32][128] in P4
    __shared__ float gsumS[16 * 32];

    const int ltid = threadIdx.x;
    const int w = ltid >> 5;
    const int lane = ltid & 31;
    const int beta = blockIdx.x;
    const int gtid = beta * NTHR + ltid;

    float* out_hs = out;
    float* out_cs = out + TYN * BB * BH;
    float* out_atts = out + 2 * TYN * BB * BH;

    float* hT = (float*)g_hT4;
    float* actF = (float*)g_act4;
    float* wS = partS;  // [b][tp] 32x128

    // init carry (transposed)
    for (int i = gtid; i < BB * BH; i += NBLK * NTHR) {
        int k = i >> 5, b = i & 31;
        hT[(k >> 2) * 128 + b * 4 + (k & 3)] = init_h[b * BH + k];
        g_cT[k * 32 + b] = init_c[b * BH + k];
    }
    gbar(beta);

    const int rg = w >> 3;        // row group (gates 2rg, 2rg+1)
    const int sp = w & 7;         // k-split

    for (int t = 0; t < TYN; ++t) {
        // ================= P1: pre1 = hT . U rows =================
        if (beta < 128) {
            u64t acc[8];
#pragma unroll
            for (int r = 0; r < 8; ++r) acc[r] = 0ull;
            const ulonglong2* actp = (const ulonglong2*)g_hT4 + sp * 16 * 32 + lane;
            const ulonglong2* b0 = (const ulonglong2*)(U + ((size_t)(rg * 2 + 0) * BH + (beta << 2)) * BH) + sp * 16;
            const ulonglong2* b1 = (const ulonglong2*)(U + ((size_t)(rg * 2 + 1) * BH + (beta << 2)) * BH) + sp * 16;
            dot8<16>(actp, b0, b1, BH / 4, acc);
#pragma unroll
            for (int r = 0; r < 8; ++r) {
                const int ri = (rg * 2 + (r >> 2)) * 4 + (r & 3);
                partS[ri * 256 + sp * 32 + lane] = fsum2(acc[r]);
            }
        }
        __syncthreads();
        if (beta < 128) {
            float v = 0.f;
#pragma unroll
            for (int s8 = 0; s8 < 8; ++s8) v += partS[w * 256 + s8 * 32 + lane];
            gsumS[w * 32 + lane] = v;
        }
        __syncthreads();
        if (beta < 128 && w < 4) {
            const int hh = (beta << 2) + w;
            const float* xt = g_xT + (size_t)t * (G4 * BB);
            float pi = gsumS[(0 * 4 + w) * 32 + lane] + xt[(0 * BH + hh) * BB + lane] + bvec[hh];
            float pf = gsumS[(1 * 4 + w) * 32 + lane] + xt[(1 * BH + hh) * BB + lane] + bvec[BH + hh];
            float po = gsumS[(2 * 4 + w) * 32 + lane] + xt[(2 * BH + hh) * BB + lane] + bvec[2 * BH + hh];
            float pg = gsumS[(3 * 4 + w) * 32 + lane] + xt[(3 * BH + hh) * BB + lane] + bvec[3 * BH + hh];
            float cold = g_cT[hh * 32 + lane];
            float hold = hT[(hh >> 2) * 128 + lane * 4 + (hh & 3)];
            float c1 = sigf(pf) * cold + sigf(pi) * tanhf(pg);
            float h1v = sigf(po) * tanhf(c1);
            float ym = y_mask[t * BB + lane];
            h1v = ym * h1v + (1.f - ym) * hold;
            g_c1T[hh * 32 + lane] = c1;
            actF[(hh >> 2) * 128 + lane * 4 + (hh & 3)] = h1v;
        }
        gbar(beta);

        // ================= P2: hproj =================
        {
            const int p = beta + 148 * w;
            if (p < 512) {
                const int d0 = p * 2;
                u64t a00 = 0, a01 = 0, a10 = 0, a11 = 0;
                const ulonglong2* act = (const ulonglong2*)g_act4;
                const ulonglong2* w0p = (const ulonglong2*)(Wcomb + (size_t)d0 * BH);
                const ulonglong2* w1p = (const ulonglong2*)(Wcomb + (size_t)(d0 + 1) * BH);
#pragma unroll 4
                for (int k4 = 0; k4 < 128; ++k4) {
                    ulonglong2 a = act[k4 * 32 + lane];
                    ulonglong2 u0 = w0p[k4];
                    ulonglong2 u1 = w1p[k4];
                    a00 = ffma2(a.x, u0.x, a00); a01 = ffma2(a.y, u0.y, a01);
                    a10 = ffma2(a.x, u1.x, a10); a11 = ffma2(a.y, u1.y, a11);
                }
                g_hproj[lane * BC + d0]     = fsum2(a00) + fsum2(a01) + b_att[d0];
                g_hproj[lane * BC + d0 + 1] = fsum2(a10) + fsum2(a11) + b_att[d0 + 1];
            }
        }
        gbar(beta);

        // ================= P3: score =================
        for (int s = w * 148 + beta; s < TXN * BB; s += NBLK * 16) {
            const int b = s & 31;
            const float4* pc = (const float4*)(g_pctx + (size_t)s * BC);
            const float4* hp = (const float4*)(g_hproj + (size_t)b * BC);
            const float4* ua = (const float4*)(Uatt);
            float acc = 0.f;
#pragma unroll
            for (int j = 0; j < 8; ++j) {
                int idx = lane + j * 32;
                float4 p = pc[idx], hh = hp[idx], u = ua[idx];
                acc = fmaf(u.x, tanh_ap(p.x + hh.x), acc);
                acc = fmaf(u.y, tanh_ap(p.y + hh.y), acc);
                acc = fmaf(u.z, tanh_ap(p.z + hh.z), acc);
                acc = fmaf(u.w, tanh_ap(p.w + hh.w), acc);
            }
#pragma unroll
            for (int o = 16; o; o >>= 1) acc += __shfl_xor_sync(0xffffffffu, acc, o);
            if (lane == 0) g_score[s] = acc * x_mask[s];
        }
        gbar(beta);

        // ================= P4a: softmax weights (block-local, all b) =========
        {
#pragma unroll
            for (int q = 0; q < 2; ++q) {
                const int b = w * 2 + q;
                float s0 = g_score[(lane +  0) * BB + b];
                float s1 = g_score[(lane + 32) * BB + b];
                float s2 = g_score[(lane + 64) * BB + b];
                float s3 = g_score[(lane + 96) * BB + b];
                float mx = fmaxf(fmaxf(s0, s1), fmaxf(s2, s3));
#pragma unroll
                for (int o = 16; o; o >>= 1) mx = fmaxf(mx, __shfl_xor_sync(0xffffffffu, mx, o));
                float e0 = __expf(s0 - mx) * x_mask[(lane +  0) * BB + b];
                float e1 = __expf(s1 - mx) * x_mask[(lane + 32) * BB + b];
                float e2 = __expf(s2 - mx) * x_mask[(lane + 64) * BB + b];
                float e3 = __expf(s3 - mx) * x_mask[(lane + 96) * BB + b];
                float sm = (e0 + e1) + (e2 + e3);
#pragma unroll
                for (int o = 16; o; o >>= 1) sm += __shfl_xor_sync(0xffffffffu, sm, o);
                const float inv = 1.f / sm;
                wS[b * 128 + lane +  0] = e0 * inv;
                wS[b * 128 + lane + 32] = e1 * inv;
                wS[b * 128 + lane + 64] = e2 * inv;
                wS[b * 128 + lane + 96] = e3 * inv;
            }
        }
        __syncthreads();

        // ================= P4b: atted[b][c] =================
        {
            const int task = w * 148 + beta;   // 1024 tasks: (b, 32-c chunk)
            if (task < 1024) {
                const int b = task >> 5;
                const int c = (task & 31) * 32 + lane;
                const float* ctxp = context + (size_t)b * BC + c;
                const float* wp = wS + b * 128;
                float a0 = 0.f, a1 = 0.f, a2 = 0.f, a3 = 0.f;
#pragma unroll 8
                for (int tp = 0; tp < TXN; tp += 4) {
                    a0 = fmaf(wp[tp + 0], ctxp[(size_t)(tp + 0) * (BB * BC)], a0);
                    a1 = fmaf(wp[tp + 1], ctxp[(size_t)(tp + 1) * (BB * BC)], a1);
                    a2 = fmaf(wp[tp + 2], ctxp[(size_t)(tp + 2) * (BB * BC)], a2);
                    a3 = fmaf(wp[tp + 3], ctxp[(size_t)(tp + 3) * (BB * BC)], a3);
                }
                const float av = (a0 + a1) + (a2 + a3);
                out_atts[(size_t)t * (BB * BC) + b * BC + c] = av;
                actF[(128 + (c >> 2)) * 128 + b * 4 + (c & 3)] = av;
            }
        }
        gbar(beta);

        // ================= P5: pre2 = h1.Ux + atted.Wx =================
        if (beta < 128) {
            u64t acc[8];
#pragma unroll
            for (int r = 0; r < 8; ++r) acc[r] = 0ull;
            {
                const ulonglong2* actp = (const ulonglong2*)g_act4 + sp * 16 * 32 + lane;
                const ulonglong2* b0 = (const ulonglong2*)(Ux + ((size_t)(rg * 2 + 0) * BH + (beta << 2)) * BH) + sp * 16;
                const ulonglong2* b1 = (const ulonglong2*)(Ux + ((size_t)(rg * 2 + 1) * BH + (beta << 2)) * BH) + sp * 16;
                dot8<16>(actp, b0, b1, BH / 4, acc);
            }
            {
                const ulonglong2* actp = (const ulonglong2*)g_act4 + (128 + sp * 32) * 32 + lane;
                const ulonglong2* b0 = (const ulonglong2*)(Wx + ((size_t)(rg * 2 + 0) * BH + (beta << 2)) * BC) + sp * 32;
                const ulonglong2* b1 = (const ulonglong2*)(Wx + ((size_t)(rg * 2 + 1) * BH + (beta << 2)) * BC) + sp * 32;
                dot8<32>(actp, b0, b1, BC / 4, acc);
            }
#pragma unroll
            for (int r = 0; r < 8; ++r) {
                const int ri = (rg * 2 + (r >> 2)) * 4 + (r & 3);
                partS[ri * 256 + sp * 32 + lane] = fsum2(acc[r]);
            }
        }
        __syncthreads();
        if (beta < 128) {
            float v = 0.f;
#pragma unroll
            for (int s8 = 0; s8 < 8; ++s8) v += partS[w * 256 + s8 * 32 + lane];
            gsumS[w * 32 + lane] = v;
        }
        __syncthreads();
        if (beta < 128 && w < 4) {
            const int hh = (beta << 2) + w;
            float pi = gsumS[(0 * 4 + w) * 32 + lane] + bx[hh];
            float pf = gsumS[(1 * 4 + w) * 32 + lane] + bx[BH + hh];
            float po = gsumS[(2 * 4 + w) * 32 + lane] + bx[2 * BH + hh];
            float pg = gsumS[(3 * 4 + w) * 32 + lane] + bx[3 * BH + hh];
            float c1 = g_c1T[hh * 32 + lane];
            float h1v = actF[(hh >> 2) * 128 + lane * 4 + (hh & 3)];
            float c2 = sigf(pf) * c1 + sigf(pi) * tanhf(pg);
            float h2 = sigf(po) * tanhf(c2);
            float ym = y_mask[t * BB + lane];
            h2 = ym * h2 + (1.f - ym) * h1v;
            out_hs[(size_t)t * (BB * BH) + lane * BH + hh] = h2;
            out_cs[(size_t)t * (BB * BH) + lane * BH + hh] = c2;
            g_cT[hh * 32 + lane] = c2;
            hT[(hh >> 2) * 128 + lane * 4 + (hh & 3)] = h2;
        }
        gbar(beta);
    }
}

// ---------------- launch ----------------
extern "C" void kernel_launch(void* const* d_in, const int* in_sizes, int n_in,
                              void* d_out, int out_size) {
    const float* y_emb   = (const float*)d_in[0];
    const float* context = (const float*)d_in[1];
    const float* init_h  = (const float*)d_in[2];
    const float* init_c  = (const float*)d_in[3];
    const float* x_mask  = (const float*)d_in[4];
    const float* y_mask  = (const float*)d_in[5];
    const float* W       = (const float*)d_in[6];
    const float* U       = (const float*)d_in[7];
    const float* bvec    = (const float*)d_in[8];
    const float* Wx      = (const float*)d_in[9];
    const float* Ux      = (const float*)d_in[10];
    const float* bx      = (const float*)d_in[11];
    const float* Wc_att  = (const float*)d_in[12];
    const float* b_att   = (const float*)d_in[13];
    const float* Wcomb   = (const float*)d_in[14];
    const float* Uatt    = (const float*)d_in[15];

    gemm_fused<<<384, 256>>>(context, Wc_att, y_emb, W);

    scan_kernel<<<NBLK, NTHR>>>(context, init_h, init_c, x_mask, y_mask,
                                U, bvec, Wx, Ux, bx, b_att, Wcomb, Uatt,
                                (float*)d_out);
}

// round 6
// speedup vs baseline: 2.0666x; 1.1387x over previous
#include <cuda_runtime.h>
#include <cuda_fp16.h>
#include <math.h>

#define BI 256
#define BH 512
#define BC 1024
#define G4 2048
#define TYN 32
#define TXN 128
#define BB 32

#define NBLK 148
#define NTHR 512   // 16 warps

// smem layout (float slots)
#define OFF_U    0        // U rows   [16][512]
#define OFF_UX   8192     // Ux rows  [16][512]
#define OFF_WX   16384    // Wx rows  [16][1024]
#define OFF_PART 32768    // partials [16][8][32]
#define OFF_GS   36864    // gsum     [16][32]
#define OFF_UA2  37376    // uatt2    [512] (u32)
#define OFF_HP2  37888    // hproj2   [32][512] (u32)
#define SMEM_FLOATS 54272
#define SMEM_BYTES (SMEM_FLOATS * 4)   // 217088

typedef unsigned long long u64t;

// ---------------- device scratch ----------------
__device__ __align__(16) unsigned g_pctx2[(size_t)TXN * BB * 512];  // [t'*32+b][c2] f16x2
__device__ float  g_xT[(size_t)TYN * G4 * BB];     // [t][g][b]
__device__ float4 g_hT4[128 * 32];                 // h carry [k4][b]
__device__ float4 g_act4[384 * 32];                // [h1 | atted] [k4][b]
__device__ float  g_cT[BH * BB];                   // c carry [h][b]
__device__ float  g_c1T[BH * BB];
__device__ __align__(16) unsigned g_hproj2[BB * 512];  // [b][d2] f16x2
__device__ __align__(16) float g_scoreQ[BB * 512];     // [b][t'*4+q]
__device__ float  g_wt[BB * TXN];                  // softmax weights [b][t']
__device__ float  g_xmT[BB * TXN];                 // x_mask [b][t']
__device__ __align__(16) unsigned g_uatt2[512];
__device__ unsigned g_cnt1[4];
__device__ unsigned g_cnt2;
__device__ unsigned g_flag;

__device__ __forceinline__ float sigf(float x) { return 1.f / (1.f + __expf(-x)); }
__device__ __forceinline__ __half2 tanh2(__half2 x) {
    unsigned xi = *(unsigned*)&x, ri;
    asm("tanh.approx.f16x2 %0, %1;" : "=r"(ri) : "r"(xi));
    return *(__half2*)&ri;
}
__device__ __forceinline__ u64t ffma2(u64t a, u64t b, u64t c) {
    u64t d; asm("fma.rn.f32x2 %0, %1, %2, %3;" : "=l"(d) : "l"(a), "l"(b), "l"(c));
    return d;
}
__device__ __forceinline__ u64t pack2(float lo, float hi) {
    u64t v; asm("mov.b64 %0, {%1, %2};" : "=l"(v) : "f"(lo), "f"(hi));
    return v;
}
__device__ __forceinline__ float fsum2(u64t v) {
    float lo, hi; asm("mov.b64 {%0, %1}, %2;" : "=f"(lo), "=f"(hi) : "l"(v));
    return lo + hi;
}
__device__ __forceinline__ float flo2(u64t v) {
    float lo, hi; asm("mov.b64 {%0, %1}, %2;" : "=f"(lo), "=f"(hi) : "l"(v));
    return lo;
}
__device__ __forceinline__ float fhi2(u64t v) {
    float lo, hi; asm("mov.b64 {%0, %1}, %2;" : "=f"(lo), "=f"(hi) : "l"(v));
    return hi;
}
__device__ __forceinline__ unsigned ldacq(const unsigned* p) {
    unsigned v;
    asm volatile("ld.acquire.gpu.global.u32 %0, [%1];" : "=r"(v) : "l"(p) : "memory");
    return v;
}

__device__ __forceinline__ void gbar(int beta) {
    __syncthreads();
    if (threadIdx.x == 0) {
        __threadfence();
        const int p = beta & 3;
        unsigned a = atomicAdd(&g_cnt1[p], 1u);
        unsigned epoch = a / 37u + 1u;
        if (a % 37u == 36u) {
            unsigned b = atomicAdd(&g_cnt2, 1u);
            if ((b & 3u) == 3u) {
                unsigned e = (b >> 2) + 1u;
                asm volatile("red.release.gpu.global.max.u32 [%0], %1;"
                             :: "l"(&g_flag), "r"(e) : "memory");
            }
        }
        while (ldacq(&g_flag) < epoch) { }
    }
    __syncthreads();
}

// ---------------- fused SGEMM (NT), double-buffered, FFMA2 ----------------
__global__ void __launch_bounds__(256) gemm_fused(const float* __restrict__ context,
                                                  const float* __restrict__ Wc_att,
                                                  const float* __restrict__ y_emb,
                                                  const float* __restrict__ W) {
    __shared__ __align__(16) float As[2][8][128];
    __shared__ __align__(16) float Bs[2][8][128];

    const int bid = blockIdx.x;
    const int job = (bid < 256) ? 0 : 1;
    const float* A;
    const float* Bm;
    int m0, n0, K, N;
    if (job == 0) {
        A = context; Bm = Wc_att; K = 1024; N = 1024;
        m0 = (bid >> 3) * 128; n0 = (bid & 7) * 128;
    } else {
        A = y_emb; Bm = W; K = 256; N = 2048;
        const int b2 = bid - 256;
        m0 = (b2 >> 4) * 128; n0 = (b2 & 15) * 128;
    }

    const int tid = threadIdx.x;
    const int tm = (tid / 16) * 8;
    const int tn = (tid % 16) * 8;
    const int lr = tid >> 1;
    const int lc = (tid & 1) * 4;

    const float* Aptr = A + (size_t)(m0 + lr) * K + lc;
    const float* Bptr = Bm + (size_t)(n0 + lr) * K + lc;

    u64t acc2[8][4];
#pragma unroll
    for (int i = 0; i < 8; ++i)
#pragma unroll
        for (int j = 0; j < 4; ++j) acc2[i][j] = 0ull;

    {
        float4 av = *(const float4*)(Aptr);
        float4 bv = *(const float4*)(Bptr);
        As[0][lc + 0][lr] = av.x; As[0][lc + 1][lr] = av.y;
        As[0][lc + 2][lr] = av.z; As[0][lc + 3][lr] = av.w;
        Bs[0][lc + 0][lr] = bv.x; Bs[0][lc + 1][lr] = bv.y;
        Bs[0][lc + 2][lr] = bv.z; Bs[0][lc + 3][lr] = bv.w;
    }
    __syncthreads();

    const int T = K / 8;
    int cur = 0;
#pragma unroll 1
    for (int kk = 0; kk < T; ++kk) {
        float4 av, bv;
        const bool more = (kk + 1 < T);
        if (more) {
            av = *(const float4*)(Aptr + (kk + 1) * 8);
            bv = *(const float4*)(Bptr + (kk + 1) * 8);
        }
#pragma unroll
        for (int k = 0; k < 8; ++k) {
            float4 a0 = *(const float4*)&As[cur][k][tm];
            float4 a1 = *(const float4*)&As[cur][k][tm + 4];
            ulonglong2 bb0 = *(const ulonglong2*)&Bs[cur][k][tn];
            ulonglong2 bb1 = *(const ulonglong2*)&Bs[cur][k][tn + 4];
            float ar[8] = {a0.x, a0.y, a0.z, a0.w, a1.x, a1.y, a1.z, a1.w};
#pragma unroll
            for (int i = 0; i < 8; ++i) {
                u64t aa = pack2(ar[i], ar[i]);
                acc2[i][0] = ffma2(aa, bb0.x, acc2[i][0]);
                acc2[i][1] = ffma2(aa, bb0.y, acc2[i][1]);
                acc2[i][2] = ffma2(aa, bb1.x, acc2[i][2]);
                acc2[i][3] = ffma2(aa, bb1.y, acc2[i][3]);
            }
        }
        if (more) {
            const int nxt = cur ^ 1;
            As[nxt][lc + 0][lr] = av.x; As[nxt][lc + 1][lr] = av.y;
            As[nxt][lc + 2][lr] = av.z; As[nxt][lc + 3][lr] = av.w;
            Bs[nxt][lc + 0][lr] = bv.x; Bs[nxt][lc + 1][lr] = bv.y;
            Bs[nxt][lc + 2][lr] = bv.z; Bs[nxt][lc + 3][lr] = bv.w;
            __syncthreads();
            cur = nxt;
        }
    }

    if (job == 0) {
        // pctx packed to f16x2: [m][c2]
#pragma unroll
        for (int i = 0; i < 8; ++i) {
            const int m = m0 + tm + i;
            uint4 ov;
            __half2 h0 = __floats2half2_rn(flo2(acc2[i][0]), fhi2(acc2[i][0]));
            __half2 h1 = __floats2half2_rn(flo2(acc2[i][1]), fhi2(acc2[i][1]));
            __half2 h2 = __floats2half2_rn(flo2(acc2[i][2]), fhi2(acc2[i][2]));
            __half2 h3 = __floats2half2_rn(flo2(acc2[i][3]), fhi2(acc2[i][3]));
            ov.x = *(unsigned*)&h0; ov.y = *(unsigned*)&h1;
            ov.z = *(unsigned*)&h2; ov.w = *(unsigned*)&h3;
            *(uint4*)(g_pctx2 + (size_t)m * 512 + (n0 + tn) / 2) = ov;
        }
    } else {
#pragma unroll
        for (int i = 0; i < 8; ++i) {
            const int m = m0 + tm + i;
            const int t = m >> 5, b = m & 31;
            float* base = g_xT + (size_t)t * (G4 * BB) + b;
            float cv[8] = {flo2(acc2[i][0]), fhi2(acc2[i][0]),
                           flo2(acc2[i][1]), fhi2(acc2[i][1]),
                           flo2(acc2[i][2]), fhi2(acc2[i][2]),
                           flo2(acc2[i][3]), fhi2(acc2[i][3])};
#pragma unroll
            for (int j = 0; j < 8; ++j)
                base[(size_t)(n0 + tn + j) * BB] = cv[j];
        }
    }
}

// ---------------- persistent scan kernel v6 ----------------
__global__ void __launch_bounds__(NTHR, 1) scan_kernel(
    const float* __restrict__ context,
    const float* __restrict__ init_h, const float* __restrict__ init_c,
    const float* __restrict__ x_mask, const float* __restrict__ y_mask,
    const float* __restrict__ U, const float* __restrict__ bvec,
    const float* __restrict__ Wx, const float* __restrict__ Ux,
    const float* __restrict__ bx, const float* __restrict__ b_att,
    const float* __restrict__ Wcomb, const float* __restrict__ Uatt,
    float* __restrict__ out)
{
    extern __shared__ __align__(16) float smw[];
    unsigned* smwu = (unsigned*)smw;

    const int ltid = threadIdx.x;
    const int w = ltid >> 5;
    const int lane = ltid & 31;
    const int beta = blockIdx.x;
    const int gtid = beta * NTHR + ltid;

    float* out_hs = out;
    float* out_cs = out + TYN * BB * BH;
    float* out_atts = out + 2 * TYN * BB * BH;

    float* hT = (float*)g_hT4;
    float* actF = (float*)g_act4;

    // ---- init: carry transpose, uatt2 pack, x_mask transpose ----
    for (int i = gtid; i < BB * BH; i += NBLK * NTHR) {
        int k = i >> 5, b = i & 31;
        hT[(k >> 2) * 128 + b * 4 + (k & 3)] = init_h[b * BH + k];
        g_cT[k * 32 + b] = init_c[b * BH + k];
    }
    if (gtid < 512) {
        __half2 hv = __floats2half2_rn(Uatt[2 * gtid], Uatt[2 * gtid + 1]);
        g_uatt2[gtid] = *(unsigned*)&hv;
    }
    for (int i = gtid; i < TXN * BB; i += NBLK * NTHR)
        g_xmT[(i & 31) * TXN + (i >> 5)] = x_mask[i];
    gbar(beta);

    // ---- one-time weight staging into smem ----
    if (beta < 128) {
        const int gate = w >> 2, hc = w & 3;
        const float* usrc  = U  + ((size_t)gate * BH + (beta << 2) + hc) * BH;
        const float* uxsrc = Ux + ((size_t)gate * BH + (beta << 2) + hc) * BH;
        const float* wxsrc = Wx + ((size_t)gate * BH + (beta << 2) + hc) * BC;
#pragma unroll
        for (int i = 0; i < 4; ++i) {
            *(float4*)&smw[OFF_U  + w * 512 + i * 128 + lane * 4] = *(const float4*)(usrc  + i * 128 + lane * 4);
            *(float4*)&smw[OFF_UX + w * 512 + i * 128 + lane * 4] = *(const float4*)(uxsrc + i * 128 + lane * 4);
        }
#pragma unroll
        for (int i = 0; i < 8; ++i)
            *(float4*)&smw[OFF_WX + w * 1024 + i * 128 + lane * 4] = *(const float4*)(wxsrc + i * 128 + lane * 4);
    }
    if (ltid < 512) smwu[OFF_UA2 + ltid] = g_uatt2[ltid];
    __syncthreads();

    const int rg = w >> 3;   // row group (rows rg*8..rg*8+7)
    const int sp = w & 7;    // k-split

    for (int t = 0; t < TYN; ++t) {
        // ================= P1: pre1 = hT . U (smem weights) =================
        if (beta < 128) {
            u64t acc[8];
#pragma unroll
            for (int r = 0; r < 8; ++r) acc[r] = 0ull;
            const ulonglong2* actp = (const ulonglong2*)g_hT4 + (sp * 16) * 32 + lane;
            const int wbase = OFF_U + (rg * 8) * 512 + sp * 64;
#pragma unroll 4
            for (int k4 = 0; k4 < 16; ++k4) {
                ulonglong2 a = actp[k4 * 32];
#pragma unroll
                for (int r = 0; r < 8; ++r) {
                    ulonglong2 wv = *(const ulonglong2*)&smw[wbase + r * 512 + k4 * 4];
                    acc[r] = ffma2(a.x, wv.x, acc[r]);
                    acc[r] = ffma2(a.y, wv.y, acc[r]);
                }
            }
#pragma unroll
            for (int r = 0; r < 8; ++r)
                smw[OFF_PART + (rg * 8 + r) * 256 + sp * 32 + lane] = fsum2(acc[r]);
        }
        __syncthreads();
        if (beta < 128) {
            float v = 0.f;
#pragma unroll
            for (int s8 = 0; s8 < 8; ++s8) v += smw[OFF_PART + w * 256 + s8 * 32 + lane];
            smw[OFF_GS + w * 32 + lane] = v;
        }
        __syncthreads();
        if (beta < 128 && w < 4) {
            const int hh = (beta << 2) + w;
            const float* xt = g_xT + (size_t)t * (G4 * BB);
            float pi = smw[OFF_GS + (0 * 4 + w) * 32 + lane] + xt[(0 * BH + hh) * BB + lane] + bvec[hh];
            float pf = smw[OFF_GS + (1 * 4 + w) * 32 + lane] + xt[(1 * BH + hh) * BB + lane] + bvec[BH + hh];
            float po = smw[OFF_GS + (2 * 4 + w) * 32 + lane] + xt[(2 * BH + hh) * BB + lane] + bvec[2 * BH + hh];
            float pg = smw[OFF_GS + (3 * 4 + w) * 32 + lane] + xt[(3 * BH + hh) * BB + lane] + bvec[3 * BH + hh];
            float cold = g_cT[hh * 32 + lane];
            float hold = hT[(hh >> 2) * 128 + lane * 4 + (hh & 3)];
            float c1 = sigf(pf) * cold + sigf(pi) * tanhf(pg);
            float h1v = sigf(po) * tanhf(c1);
            float ym = y_mask[t * BB + lane];
            h1v = ym * h1v + (1.f - ym) * hold;
            g_c1T[hh * 32 + lane] = c1;
            actF[(hh >> 2) * 128 + lane * 4 + (hh & 3)] = h1v;
        }
        gbar(beta);

        // ================= P2: hproj (f16x2 epilogue) =================
        {
            const int p = beta + 148 * w;
            if (p < 512) {
                const int d0 = p * 2;
                u64t a00 = 0, a01 = 0, a10 = 0, a11 = 0;
                const ulonglong2* act = (const ulonglong2*)g_act4;
                const ulonglong2* w0p = (const ulonglong2*)(Wcomb + (size_t)d0 * BH);
                const ulonglong2* w1p = (const ulonglong2*)(Wcomb + (size_t)(d0 + 1) * BH);
#pragma unroll 4
                for (int k4 = 0; k4 < 128; ++k4) {
                    ulonglong2 a = act[k4 * 32 + lane];
                    ulonglong2 u0 = w0p[k4];
                    ulonglong2 u1 = w1p[k4];
                    a00 = ffma2(a.x, u0.x, a00); a01 = ffma2(a.y, u0.y, a01);
                    a10 = ffma2(a.x, u1.x, a10); a11 = ffma2(a.y, u1.y, a11);
                }
                float v0 = fsum2(a00) + fsum2(a01) + b_att[d0];
                float v1 = fsum2(a10) + fsum2(a11) + b_att[d0 + 1];
                __half2 hv = __floats2half2_rn(v0, v1);
                g_hproj2[lane * 512 + p] = *(unsigned*)&hv;
            }
        }
        gbar(beta);

        // ================= P3: scores via tanh.f16x2 (quarter tasks) ========
        for (int i = ltid; i < 32 * 512; i += NTHR) smwu[OFF_HP2 + i] = g_hproj2[i];
        __syncthreads();
        for (int task = w * 148 + beta; task < 16384; task += NBLK * 16) {
            const int s = task >> 2, q = task & 3, b = s & 31;
            uint4 pc = *(const uint4*)(g_pctx2 + (size_t)s * 512 + q * 128 + lane * 4);
            uint4 hp = *(const uint4*)(smwu + OFF_HP2 + b * 512 + q * 128 + lane * 4);
            uint4 ua = *(const uint4*)(smwu + OFF_UA2 + q * 128 + lane * 4);
            __half2 acc2 = __floats2half2_rn(0.f, 0.f);
            acc2 = __hfma2(*(__half2*)&ua.x, tanh2(__hadd2(*(__half2*)&pc.x, *(__half2*)&hp.x)), acc2);
            acc2 = __hfma2(*(__half2*)&ua.y, tanh2(__hadd2(*(__half2*)&pc.y, *(__half2*)&hp.y)), acc2);
            acc2 = __hfma2(*(__half2*)&ua.z, tanh2(__hadd2(*(__half2*)&pc.z, *(__half2*)&hp.z)), acc2);
            acc2 = __hfma2(*(__half2*)&ua.w, tanh2(__hadd2(*(__half2*)&pc.w, *(__half2*)&hp.w)), acc2);
            float2 f2 = __half22float2(acc2);
            float v = f2.x + f2.y;
#pragma unroll
            for (int o = 16; o; o >>= 1) v += __shfl_xor_sync(0xffffffffu, v, o);
            if (lane == 0) g_scoreQ[b * 512 + (s >> 5) * 4 + q] = v;
        }
        gbar(beta);

        // ================= P4a: global softmax (blocks 0..1) =================
        if (beta < 2) {
            const int b = beta * 16 + w;
            float sc[4], xm[4];
#pragma unroll
            for (int j = 0; j < 4; ++j) {
                float4 vq = *(const float4*)&g_scoreQ[b * 512 + (lane + 32 * j) * 4];
                xm[j] = g_xmT[b * TXN + lane + 32 * j];
                sc[j] = ((vq.x + vq.y) + (vq.z + vq.w)) * xm[j];
            }
            float mx = fmaxf(fmaxf(sc[0], sc[1]), fmaxf(sc[2], sc[3]));
#pragma unroll
            for (int o = 16; o; o >>= 1) mx = fmaxf(mx, __shfl_xor_sync(0xffffffffu, mx, o));
            float e[4], sm = 0.f;
#pragma unroll
            for (int j = 0; j < 4; ++j) { e[j] = __expf(sc[j] - mx) * xm[j]; sm += e[j]; }
#pragma unroll
            for (int o = 16; o; o >>= 1) sm += __shfl_xor_sync(0xffffffffu, sm, o);
            const float inv = 1.f / sm;
#pragma unroll
            for (int j = 0; j < 4; ++j) g_wt[b * TXN + lane + 32 * j] = e[j] * inv;
        }
        gbar(beta);

        // ================= P4b: atted[b][c] =================
        {
            const int task = w * 148 + beta;
            if (task < 1024) {
                const int b = task >> 5;
                const int c = (task & 31) * 32 + lane;
                const float* ctxp = context + (size_t)b * BC + c;
                const float* wp = g_wt + b * TXN;
                float a0 = 0.f, a1 = 0.f, a2 = 0.f, a3 = 0.f;
#pragma unroll 8
                for (int tp = 0; tp < TXN; tp += 4) {
                    a0 = fmaf(wp[tp + 0], ctxp[(size_t)(tp + 0) * (BB * BC)], a0);
                    a1 = fmaf(wp[tp + 1], ctxp[(size_t)(tp + 1) * (BB * BC)], a1);
                    a2 = fmaf(wp[tp + 2], ctxp[(size_t)(tp + 2) * (BB * BC)], a2);
                    a3 = fmaf(wp[tp + 3], ctxp[(size_t)(tp + 3) * (BB * BC)], a3);
                }
                const float av = (a0 + a1) + (a2 + a3);
                out_atts[(size_t)t * (BB * BC) + b * BC + c] = av;
                actF[(128 + (c >> 2)) * 128 + b * 4 + (c & 3)] = av;
            }
        }
        gbar(beta);

        // ================= P5: pre2 = h1.Ux + atted.Wx (smem weights) ========
        if (beta < 128) {
            u64t acc[8];
#pragma unroll
            for (int r = 0; r < 8; ++r) acc[r] = 0ull;
            {
                const ulonglong2* actp = (const ulonglong2*)g_act4 + (sp * 16) * 32 + lane;
                const int wbase = OFF_UX + (rg * 8) * 512 + sp * 64;
#pragma unroll 4
                for (int k4 = 0; k4 < 16; ++k4) {
                    ulonglong2 a = actp[k4 * 32];
#pragma unroll
                    for (int r = 0; r < 8; ++r) {
                        ulonglong2 wv = *(const ulonglong2*)&smw[wbase + r * 512 + k4 * 4];
                        acc[r] = ffma2(a.x, wv.x, acc[r]);
                        acc[r] = ffma2(a.y, wv.y, acc[r]);
                    }
                }
            }
            {
                const ulonglong2* actp = (const ulonglong2*)g_act4 + (128 + sp * 32) * 32 + lane;
                const int wbase = OFF_WX + (rg * 8) * 1024 + sp * 128;
#pragma unroll 4
                for (int k4 = 0; k4 < 32; ++k4) {
                    ulonglong2 a = actp[k4 * 32];
#pragma unroll
                    for (int r = 0; r < 8; ++r) {
                        ulonglong2 wv = *(const ulonglong2*)&smw[wbase + r * 1024 + k4 * 4];
                        acc[r] = ffma2(a.x, wv.x, acc[r]);
                        acc[r] = ffma2(a.y, wv.y, acc[r]);
                    }
                }
            }
#pragma unroll
            for (int r = 0; r < 8; ++r)
                smw[OFF_PART + (rg * 8 + r) * 256 + sp * 32 + lane] = fsum2(acc[r]);
        }
        __syncthreads();
        if (beta < 128) {
            float v = 0.f;
#pragma unroll
            for (int s8 = 0; s8 < 8; ++s8) v += smw[OFF_PART + w * 256 + s8 * 32 + lane];
            smw[OFF_GS + w * 32 + lane] = v;
        }
        __syncthreads();
        if (beta < 128 && w < 4) {
            const int hh = (beta << 2) + w;
            float pi = smw[OFF_GS + (0 * 4 + w) * 32 + lane] + bx[hh];
            float pf = smw[OFF_GS + (1 * 4 + w) * 32 + lane] + bx[BH + hh];
            float po = smw[OFF_GS + (2 * 4 + w) * 32 + lane] + bx[2 * BH + hh];
            float pg = smw[OFF_GS + (3 * 4 + w) * 32 + lane] + bx[3 * BH + hh];
            float c1 = g_c1T[hh * 32 + lane];
            float h1v = actF[(hh >> 2) * 128 + lane * 4 + (hh & 3)];
            float c2 = sigf(pf) * c1 + sigf(pi) * tanhf(pg);
            float h2 = sigf(po) * tanhf(c2);
            float ym = y_mask[t * BB + lane];
            h2 = ym * h2 + (1.f - ym) * h1v;
            out_hs[(size_t)t * (BB * BH) + lane * BH + hh] = h2;
            out_cs[(size_t)t * (BB * BH) + lane * BH + hh] = c2;
            g_cT[hh * 32 + lane] = c2;
            hT[(hh >> 2) * 128 + lane * 4 + (hh & 3)] = h2;
        }
        gbar(beta);
    }
}

// ---------------- launch ----------------
extern "C" void kernel_launch(void* const* d_in, const int* in_sizes, int n_in,
                              void* d_out, int out_size) {
    const float* y_emb   = (const float*)d_in[0];
    const float* context = (const float*)d_in[1];
    const float* init_h  = (const float*)d_in[2];
    const float* init_c  = (const float*)d_in[3];
    const float* x_mask  = (const float*)d_in[4];
    const float* y_mask  = (const float*)d_in[5];
    const float* W       = (const float*)d_in[6];
    const float* U       = (const float*)d_in[7];
    const float* bvec    = (const float*)d_in[8];
    const float* Wx      = (const float*)d_in[9];
    const float* Ux      = (const float*)d_in[10];
    const float* bx      = (const float*)d_in[11];
    const float* Wc_att  = (const float*)d_in[12];
    const float* b_att   = (const float*)d_in[13];
    const float* Wcomb   = (const float*)d_in[14];
    const float* Uatt    = (const float*)d_in[15];

    cudaFuncSetAttribute(scan_kernel, cudaFuncAttributeMaxDynamicSharedMemorySize, SMEM_BYTES);

    gemm_fused<<<384, 256>>>(context, Wc_att, y_emb, W);

    scan_kernel<<<NBLK, NTHR, SMEM_BYTES>>>(context, init_h, init_c, x_mask, y_mask,
                                            U, bvec, Wx, Ux, bx, b_att, Wcomb, Uatt,
                                            (float*)d_out);
}

// round 7
// speedup vs baseline: 2.2853x; 1.1058x over previous
#include <cuda_runtime.h>
#include <cuda_fp16.h>
#include <math.h>

#define BI 256
#define BH 512
#define BC 1024
#define G4 2048
#define TYN 32
#define TXN 128
#define BB 32

#define NBLK 148
#define NTHR 512   // 16 warps

// smem layout (float slots)
#define OFF_U    0        // U rows   [16][512]
#define OFF_WX   8192     // Wx rows  [16][1024]
#define OFF_PART 24576    // partials [16][8][32]
#define OFF_GS   28672    // gsum     [16][32]
#define OFF_UA2  29184    // uatt2    [512] (u32)
#define OFF_WT   29696    // per-warp softmax wt [16][128]
#define SMEM_FLOATS 31744
#define SMEM_BYTES (SMEM_FLOATS * 4)   // 126976

typedef unsigned long long u64t;

// ---------------- device scratch ----------------
__device__ __align__(16) unsigned g_pctx2[(size_t)TXN * BB * 512];  // [t'*32+b][c2] f16x2
__device__ float  g_xT[(size_t)TYN * G4 * BB];     // [t][g][b]
__device__ float4 g_hT4[128 * 32];                 // h carry [k4][b]
__device__ float4 g_act4[384 * 32];                // [h1 | atted] [k4][b]
__device__ float  g_cT[BH * BB];                   // c carry [h][b]
__device__ float  g_c1T[BH * BB];
__device__ __align__(16) float g_hpp[4][BB * BC];  // hproj k-chunk partials [ch][b][d]
__device__ float  g_p2a[4][G4 * BB];               // Ux.h1 k-chunk partials [ch][row][b]
__device__ __align__(16) float g_scoreQ[BB * 512]; // [b][t'*4+q]
__device__ float  g_xmT[BB * TXN];                 // x_mask [b][t']
__device__ __align__(16) unsigned g_uatt2[512];
__device__ unsigned g_cnt1[4];
__device__ unsigned g_cnt2;
__device__ unsigned g_flag;

__device__ __forceinline__ float sigf(float x) { return 1.f / (1.f + __expf(-x)); }
__device__ __forceinline__ __half2 tanh2(__half2 x) {
    unsigned xi = *(unsigned*)&x, ri;
    asm("tanh.approx.f16x2 %0, %1;" : "=r"(ri) : "r"(xi));
    return *(__half2*)&ri;
}
__device__ __forceinline__ u64t ffma2(u64t a, u64t b, u64t c) {
    u64t d; asm("fma.rn.f32x2 %0, %1, %2, %3;" : "=l"(d) : "l"(a), "l"(b), "l"(c));
    return d;
}
__device__ __forceinline__ u64t pack2(float lo, float hi) {
    u64t v; asm("mov.b64 %0, {%1, %2};" : "=l"(v) : "f"(lo), "f"(hi));
    return v;
}
__device__ __forceinline__ float fsum2(u64t v) {
    float lo, hi; asm("mov.b64 {%0, %1}, %2;" : "=f"(lo), "=f"(hi) : "l"(v));
    return lo + hi;
}
__device__ __forceinline__ float flo2(u64t v) {
    float lo, hi; asm("mov.b64 {%0, %1}, %2;" : "=f"(lo), "=f"(hi) : "l"(v));
    return lo;
}
__device__ __forceinline__ float fhi2(u64t v) {
    float lo, hi; asm("mov.b64 {%0, %1}, %2;" : "=f"(lo), "=f"(hi) : "l"(v));
    return hi;
}
__device__ __forceinline__ unsigned ldacq(const unsigned* p) {
    unsigned v;
    asm volatile("ld.acquire.gpu.global.u32 %0, [%1];" : "=r"(v) : "l"(p) : "memory");
    return v;
}

__device__ __forceinline__ void gbar(int beta) {
    __syncthreads();
    if (threadIdx.x == 0) {
        __threadfence();
        const int p = beta & 3;
        unsigned a = atomicAdd(&g_cnt1[p], 1u);
        unsigned epoch = a / 37u + 1u;
        if (a % 37u == 36u) {
            unsigned b = atomicAdd(&g_cnt2, 1u);
            if ((b & 3u) == 3u) {
                unsigned e = (b >> 2) + 1u;
                asm volatile("red.release.gpu.global.max.u32 [%0], %1;"
                             :: "l"(&g_flag), "r"(e) : "memory");
            }
        }
        while (ldacq(&g_flag) < epoch) { }
    }
    __syncthreads();
}

// ---------------- fused SGEMM (NT), double-buffered, FFMA2 ----------------
__global__ void __launch_bounds__(256) gemm_fused(const float* __restrict__ context,
                                                  const float* __restrict__ Wc_att,
                                                  const float* __restrict__ y_emb,
                                                  const float* __restrict__ W) {
    __shared__ __align__(16) float As[2][8][128];
    __shared__ __align__(16) float Bs[2][8][128];

    const int bid = blockIdx.x;
    const int job = (bid < 256) ? 0 : 1;
    const float* A;
    const float* Bm;
    int m0, n0, K, N;
    if (job == 0) {
        A = context; Bm = Wc_att; K = 1024; N = 1024;
        m0 = (bid >> 3) * 128; n0 = (bid & 7) * 128;
    } else {
        A = y_emb; Bm = W; K = 256; N = 2048;
        const int b2 = bid - 256;
        m0 = (b2 >> 4) * 128; n0 = (b2 & 15) * 128;
    }

    const int tid = threadIdx.x;
    const int tm = (tid / 16) * 8;
    const int tn = (tid % 16) * 8;
    const int lr = tid >> 1;
    const int lc = (tid & 1) * 4;

    const float* Aptr = A + (size_t)(m0 + lr) * K + lc;
    const float* Bptr = Bm + (size_t)(n0 + lr) * K + lc;

    u64t acc2[8][4];
#pragma unroll
    for (int i = 0; i < 8; ++i)
#pragma unroll
        for (int j = 0; j < 4; ++j) acc2[i][j] = 0ull;

    {
        float4 av = *(const float4*)(Aptr);
        float4 bv = *(const float4*)(Bptr);
        As[0][lc + 0][lr] = av.x; As[0][lc + 1][lr] = av.y;
        As[0][lc + 2][lr] = av.z; As[0][lc + 3][lr] = av.w;
        Bs[0][lc + 0][lr] = bv.x; Bs[0][lc + 1][lr] = bv.y;
        Bs[0][lc + 2][lr] = bv.z; Bs[0][lc + 3][lr] = bv.w;
    }
    __syncthreads();

    const int T = K / 8;
    int cur = 0;
#pragma unroll 1
    for (int kk = 0; kk < T; ++kk) {
        float4 av, bv;
        const bool more = (kk + 1 < T);
        if (more) {
            av = *(const float4*)(Aptr + (kk + 1) * 8);
            bv = *(const float4*)(Bptr + (kk + 1) * 8);
        }
#pragma unroll
        for (int k = 0; k < 8; ++k) {
            float4 a0 = *(const float4*)&As[cur][k][tm];
            float4 a1 = *(const float4*)&As[cur][k][tm + 4];
            ulonglong2 bb0 = *(const ulonglong2*)&Bs[cur][k][tn];
            ulonglong2 bb1 = *(const ulonglong2*)&Bs[cur][k][tn + 4];
            float ar[8] = {a0.x, a0.y, a0.z, a0.w, a1.x, a1.y, a1.z, a1.w};
#pragma unroll
            for (int i = 0; i < 8; ++i) {
                u64t aa = pack2(ar[i], ar[i]);
                acc2[i][0] = ffma2(aa, bb0.x, acc2[i][0]);
                acc2[i][1] = ffma2(aa, bb0.y, acc2[i][1]);
                acc2[i][2] = ffma2(aa, bb1.x, acc2[i][2]);
                acc2[i][3] = ffma2(aa, bb1.y, acc2[i][3]);
            }
        }
        if (more) {
            const int nxt = cur ^ 1;
            As[nxt][lc + 0][lr] = av.x; As[nxt][lc + 1][lr] = av.y;
            As[nxt][lc + 2][lr] = av.z; As[nxt][lc + 3][lr] = av.w;
            Bs[nxt][lc + 0][lr] = bv.x; Bs[nxt][lc + 1][lr] = bv.y;
            Bs[nxt][lc + 2][lr] = bv.z; Bs[nxt][lc + 3][lr] = bv.w;
            __syncthreads();
            cur = nxt;
        }
    }

    if (job == 0) {
#pragma unroll
        for (int i = 0; i < 8; ++i) {
            const int m = m0 + tm + i;
            uint4 ov;
            __half2 h0 = __floats2half2_rn(flo2(acc2[i][0]), fhi2(acc2[i][0]));
            __half2 h1 = __floats2half2_rn(flo2(acc2[i][1]), fhi2(acc2[i][1]));
            __half2 h2 = __floats2half2_rn(flo2(acc2[i][2]), fhi2(acc2[i][2]));
            __half2 h3 = __floats2half2_rn(flo2(acc2[i][3]), fhi2(acc2[i][3]));
            ov.x = *(unsigned*)&h0; ov.y = *(unsigned*)&h1;
            ov.z = *(unsigned*)&h2; ov.w = *(unsigned*)&h3;
            *(uint4*)(g_pctx2 + (size_t)m * 512 + (n0 + tn) / 2) = ov;
        }
    } else {
#pragma unroll
        for (int i = 0; i < 8; ++i) {
            const int m = m0 + tm + i;
            const int t = m >> 5, b = m & 31;
            float* base = g_xT + (size_t)t * (G4 * BB) + b;
            float cv[8] = {flo2(acc2[i][0]), fhi2(acc2[i][0]),
                           flo2(acc2[i][1]), fhi2(acc2[i][1]),
                           flo2(acc2[i][2]), fhi2(acc2[i][2]),
                           flo2(acc2[i][3]), fhi2(acc2[i][3])};
#pragma unroll
            for (int j = 0; j < 8; ++j)
                base[(size_t)(n0 + tn + j) * BB] = cv[j];
        }
    }
}

// dot8: 8 rows (2 groups of 4, stride rowstride_u2) x act slice
template<int NK4>
__device__ __forceinline__ void dot8(const ulonglong2* __restrict__ actp,
                                     const ulonglong2* __restrict__ base0,
                                     const ulonglong2* __restrict__ base1,
                                     int rowstride_u2, u64t acc[8]) {
#pragma unroll 4
    for (int k = 0; k < NK4; ++k) {
        ulonglong2 a = actp[k * 32];
        {
            ulonglong2 w0 = base0[k];
            ulonglong2 w1 = base0[rowstride_u2 + k];
            ulonglong2 w2 = base0[2 * rowstride_u2 + k];
            ulonglong2 w3 = base0[3 * rowstride_u2 + k];
            acc[0] = ffma2(a.x, w0.x, acc[0]); acc[0] = ffma2(a.y, w0.y, acc[0]);
            acc[1] = ffma2(a.x, w1.x, acc[1]); acc[1] = ffma2(a.y, w1.y, acc[1]);
            acc[2] = ffma2(a.x, w2.x, acc[2]); acc[2] = ffma2(a.y, w2.y, acc[2]);
            acc[3] = ffma2(a.x, w3.x, acc[3]); acc[3] = ffma2(a.y, w3.y, acc[3]);
        }
        {
            ulonglong2 w0 = base1[k];
            ulonglong2 w1 = base1[rowstride_u2 + k];
            ulonglong2 w2 = base1[2 * rowstride_u2 + k];
            ulonglong2 w3 = base1[3 * rowstride_u2 + k];
            acc[4] = ffma2(a.x, w0.x, acc[4]); acc[4] = ffma2(a.y, w0.y, acc[4]);
            acc[5] = ffma2(a.x, w1.x, acc[5]); acc[5] = ffma2(a.y, w1.y, acc[5]);
            acc[6] = ffma2(a.x, w2.x, acc[6]); acc[6] = ffma2(a.y, w2.y, acc[6]);
            acc[7] = ffma2(a.x, w3.x, acc[7]); acc[7] = ffma2(a.y, w3.y, acc[7]);
        }
    }
}

// ---------------- persistent scan kernel v7 ----------------
__global__ void __launch_bounds__(NTHR, 1) scan_kernel(
    const float* __restrict__ context,
    const float* __restrict__ init_h, const float* __restrict__ init_c,
    const float* __restrict__ x_mask, const float* __restrict__ y_mask,
    const float* __restrict__ U, const float* __restrict__ bvec,
    const float* __restrict__ Wx, const float* __restrict__ Ux,
    const float* __restrict__ bx, const float* __restrict__ b_att,
    const float* __restrict__ Wcomb, const float* __restrict__ Uatt,
    float* __restrict__ out)
{
    extern __shared__ __align__(16) float smw[];
    unsigned* smwu = (unsigned*)smw;

    const int ltid = threadIdx.x;
    const int w = ltid >> 5;
    const int lane = ltid & 31;
    const int beta = blockIdx.x;
    const int gtid = beta * NTHR + ltid;
    const int gw = w * NBLK + beta;   // spread warp id

    float* out_hs = out;
    float* out_cs = out + TYN * BB * BH;
    float* out_atts = out + 2 * TYN * BB * BH;

    float* hT = (float*)g_hT4;
    float* actF = (float*)g_act4;

    // ---- init ----
    for (int i = gtid; i < BB * BH; i += NBLK * NTHR) {
        int k = i >> 5, b = i & 31;
        hT[(k >> 2) * 128 + b * 4 + (k & 3)] = init_h[b * BH + k];
        g_cT[k * 32 + b] = init_c[b * BH + k];
    }
    if (gtid < 512) {
        __half2 hv = __floats2half2_rn(Uatt[2 * gtid], Uatt[2 * gtid + 1]);
        g_uatt2[gtid] = *(unsigned*)&hv;
    }
    for (int i = gtid; i < TXN * BB; i += NBLK * NTHR)
        g_xmT[(i & 31) * TXN + (i >> 5)] = x_mask[i];
    gbar(beta);

    // ---- one-time weight staging: U and Wx rows for this block's 4 h-cols ----
    if (beta < 128) {
        const int gate = w >> 2, hc = w & 3;
        const float* usrc  = U  + ((size_t)gate * BH + (beta << 2) + hc) * BH;
        const float* wxsrc = Wx + ((size_t)gate * BH + (beta << 2) + hc) * BC;
#pragma unroll
        for (int i = 0; i < 4; ++i)
            *(float4*)&smw[OFF_U  + w * 512 + i * 128 + lane * 4] = *(const float4*)(usrc  + i * 128 + lane * 4);
#pragma unroll
        for (int i = 0; i < 8; ++i)
            *(float4*)&smw[OFF_WX + w * 1024 + i * 128 + lane * 4] = *(const float4*)(wxsrc + i * 128 + lane * 4);
    }
    if (ltid < 512) smwu[OFF_UA2 + ltid] = g_uatt2[ltid];
    __syncthreads();

    const int rg = w >> 3;   // row group
    const int sp = w & 7;    // k-split

    for (int t = 0; t < TYN; ++t) {
        // ================= P1: pre1 = hT . U (smem) + cell1 =================
        if (beta < 128) {
            u64t acc[8];
#pragma unroll
            for (int r = 0; r < 8; ++r) acc[r] = 0ull;
            const ulonglong2* actp = (const ulonglong2*)g_hT4 + (sp * 16) * 32 + lane;
            const int wbase = OFF_U + (rg * 8) * 512 + sp * 64;
#pragma unroll 4
            for (int k4 = 0; k4 < 16; ++k4) {
                ulonglong2 a = actp[k4 * 32];
#pragma unroll
                for (int r = 0; r < 8; ++r) {
                    ulonglong2 wv = *(const ulonglong2*)&smw[wbase + r * 512 + k4 * 4];
                    acc[r] = ffma2(a.x, wv.x, acc[r]);
                    acc[r] = ffma2(a.y, wv.y, acc[r]);
                }
            }
#pragma unroll
            for (int r = 0; r < 8; ++r)
                smw[OFF_PART + (rg * 8 + r) * 256 + sp * 32 + lane] = fsum2(acc[r]);
        }
        __syncthreads();
        if (beta < 128) {
            float v = 0.f;
#pragma unroll
            for (int s8 = 0; s8 < 8; ++s8) v += smw[OFF_PART + w * 256 + s8 * 32 + lane];
            smw[OFF_GS + w * 32 + lane] = v;
        }
        __syncthreads();
        if (beta < 128 && w < 4) {
            const int hh = (beta << 2) + w;
            const float* xt = g_xT + (size_t)t * (G4 * BB);
            float pi = smw[OFF_GS + (0 * 4 + w) * 32 + lane] + xt[(0 * BH + hh) * BB + lane] + bvec[hh];
            float pf = smw[OFF_GS + (1 * 4 + w) * 32 + lane] + xt[(1 * BH + hh) * BB + lane] + bvec[BH + hh];
            float po = smw[OFF_GS + (2 * 4 + w) * 32 + lane] + xt[(2 * BH + hh) * BB + lane] + bvec[2 * BH + hh];
            float pg = smw[OFF_GS + (3 * 4 + w) * 32 + lane] + xt[(3 * BH + hh) * BB + lane] + bvec[3 * BH + hh];
            float cold = g_cT[hh * 32 + lane];
            float hold = hT[(hh >> 2) * 128 + lane * 4 + (hh & 3)];
            float c1 = sigf(pf) * cold + sigf(pi) * tanhf(pg);
            float h1v = sigf(po) * tanhf(c1);
            float ym = y_mask[t * BB + lane];
            h1v = ym * h1v + (1.f - ym) * hold;
            g_c1T[hh * 32 + lane] = c1;
            actF[(hh >> 2) * 128 + lane * 4 + (hh & 3)] = h1v;
        }
        gbar(beta);

        // ================= W2: hproj chunks + Ux.h1 chunks (overlapped) ======
        if (gw < 512) {
            // hproj: octet o of 8 d-rows, k-chunk ch of 128
            const int o = gw >> 2, ch = gw & 3;
            u64t acc[8];
#pragma unroll
            for (int r = 0; r < 8; ++r) acc[r] = 0ull;
            const ulonglong2* actp = (const ulonglong2*)g_act4 + (ch * 32) * 32 + lane;
            const ulonglong2* b0 = (const ulonglong2*)(Wcomb + (size_t)(o * 8) * BH) + ch * 32;
            const ulonglong2* b1 = (const ulonglong2*)(Wcomb + (size_t)(o * 8 + 4) * BH) + ch * 32;
            dot8<32>(actp, b0, b1, BH / 4, acc);
            float* dst = g_hpp[ch] + lane * BC + o * 8;
#pragma unroll
            for (int r = 0; r < 8; ++r) {
                float v = fsum2(acc[r]);
                if (ch == 0) v += b_att[o * 8 + r];
                dst[r] = v;
            }
        } else if (gw < 1536) {
            // pre2a: Ux.h1, octet of 8 gate-rows, k-chunk ch
            const int q2 = gw - 512;
            const int o = q2 >> 2, ch = q2 & 3;
            u64t acc[8];
#pragma unroll
            for (int r = 0; r < 8; ++r) acc[r] = 0ull;
            const ulonglong2* actp = (const ulonglong2*)g_act4 + (ch * 32) * 32 + lane;
            const ulonglong2* b0 = (const ulonglong2*)(Ux + (size_t)(o * 8) * BH) + ch * 32;
            const ulonglong2* b1 = (const ulonglong2*)(Ux + (size_t)(o * 8 + 4) * BH) + ch * 32;
            dot8<32>(actp, b0, b1, BH / 4, acc);
            float* dst = g_p2a[ch] + (size_t)(o * 8) * 32 + lane;
#pragma unroll
            for (int r = 0; r < 8; ++r) dst[r * 32] = fsum2(acc[r]);
        }
        gbar(beta);

        // ================= P3: scores via tanh.f16x2 =================
#pragma unroll 1
        for (int task = gw; task < 16384; task += NBLK * 16) {
            const int s = task >> 2, q = task & 3, b = s & 31;
            uint4 pc = *(const uint4*)(g_pctx2 + (size_t)s * 512 + q * 128 + lane * 4);
            const int hoff = b * BC + q * 256 + lane * 8;
            float4 p0a = *(const float4*)(g_hpp[0] + hoff);
            float4 p0b = *(const float4*)(g_hpp[0] + hoff + 4);
            float4 p1a = *(const float4*)(g_hpp[1] + hoff);
            float4 p1b = *(const float4*)(g_hpp[1] + hoff + 4);
            float4 p2a = *(const float4*)(g_hpp[2] + hoff);
            float4 p2b = *(const float4*)(g_hpp[2] + hoff + 4);
            float4 p3a = *(const float4*)(g_hpp[3] + hoff);
            float4 p3b = *(const float4*)(g_hpp[3] + hoff + 4);
            uint4 ua = *(const uint4*)(smwu + OFF_UA2 + q * 128 + lane * 4);
            __half2 hp0 = __floats2half2_rn((p0a.x + p1a.x) + (p2a.x + p3a.x),
                                            (p0a.y + p1a.y) + (p2a.y + p3a.y));
            __half2 hp1 = __floats2half2_rn((p0a.z + p1a.z) + (p2a.z + p3a.z),
                                            (p0a.w + p1a.w) + (p2a.w + p3a.w));
            __half2 hp2 = __floats2half2_rn((p0b.x + p1b.x) + (p2b.x + p3b.x),
                                            (p0b.y + p1b.y) + (p2b.y + p3b.y));
            __half2 hp3 = __floats2half2_rn((p0b.z + p1b.z) + (p2b.z + p3b.z),
                                            (p0b.w + p1b.w) + (p2b.w + p3b.w));
            __half2 acc2 = __floats2half2_rn(0.f, 0.f);
            acc2 = __hfma2(*(__half2*)&ua.x, tanh2(__hadd2(*(__half2*)&pc.x, hp0)), acc2);
            acc2 = __hfma2(*(__half2*)&ua.y, tanh2(__hadd2(*(__half2*)&pc.y, hp1)), acc2);
            acc2 = __hfma2(*(__half2*)&ua.z, tanh2(__hadd2(*(__half2*)&pc.z, hp2)), acc2);
            acc2 = __hfma2(*(__half2*)&ua.w, tanh2(__hadd2(*(__half2*)&pc.w, hp3)), acc2);
            float2 f2 = __half22float2(acc2);
            float v = f2.x + f2.y;
#pragma unroll
            for (int o2 = 16; o2; o2 >>= 1) v += __shfl_xor_sync(0xffffffffu, v, o2);
            if (lane == 0) g_scoreQ[b * 512 + (s >> 5) * 4 + q] = v;
        }
        gbar(beta);

        // ================= P4: per-task softmax + atted =================
        if (gw < 1024) {
            const int b = gw >> 5;
            const int c = (gw & 31) * 32 + lane;
            // softmax for b (redundant per task, cheap)
            float sc[4], xm[4];
#pragma unroll
            for (int j = 0; j < 4; ++j) {
                float4 vq = *(const float4*)&g_scoreQ[b * 512 + (lane + 32 * j) * 4];
                xm[j] = g_xmT[b * TXN + lane + 32 * j];
                sc[j] = ((vq.x + vq.y) + (vq.z + vq.w)) * xm[j];
            }
            float mx = fmaxf(fmaxf(sc[0], sc[1]), fmaxf(sc[2], sc[3]));
#pragma unroll
            for (int o2 = 16; o2; o2 >>= 1) mx = fmaxf(mx, __shfl_xor_sync(0xffffffffu, mx, o2));
            float e[4], sm = 0.f;
#pragma unroll
            for (int j = 0; j < 4; ++j) { e[j] = __expf(sc[j] - mx) * xm[j]; sm += e[j]; }
#pragma unroll
            for (int o2 = 16; o2; o2 >>= 1) sm += __shfl_xor_sync(0xffffffffu, sm, o2);
            const float inv = 1.f / sm;
#pragma unroll
            for (int j = 0; j < 4; ++j) smw[OFF_WT + w * 128 + lane + 32 * j] = e[j] * inv;
            __syncwarp();
            // atted
            const float* ctxp = context + (size_t)b * BC + c;
            const float* wp = smw + OFF_WT + w * 128;
            float a0 = 0.f, a1 = 0.f, a2 = 0.f, a3 = 0.f;
#pragma unroll 8
            for (int tp = 0; tp < TXN; tp += 4) {
                a0 = fmaf(wp[tp + 0], ctxp[(size_t)(tp + 0) * (BB * BC)], a0);
                a1 = fmaf(wp[tp + 1], ctxp[(size_t)(tp + 1) * (BB * BC)], a1);
                a2 = fmaf(wp[tp + 2], ctxp[(size_t)(tp + 2) * (BB * BC)], a2);
                a3 = fmaf(wp[tp + 3], ctxp[(size_t)(tp + 3) * (BB * BC)], a3);
            }
            const float av = (a0 + a1) + (a2 + a3);
            out_atts[(size_t)t * (BB * BC) + b * BC + c] = av;
            actF[(128 + (c >> 2)) * 128 + b * 4 + (c & 3)] = av;
        }
        gbar(beta);

        // ================= P5: Wx.atted (smem) + pre2a + cell2 =================
        if (beta < 128) {
            u64t acc[8];
#pragma unroll
            for (int r = 0; r < 8; ++r) acc[r] = 0ull;
            const ulonglong2* actp = (const ulonglong2*)g_act4 + (128 + sp * 32) * 32 + lane;
            const int wbase = OFF_WX + (rg * 8) * 1024 + sp * 128;
#pragma unroll 4
            for (int k4 = 0; k4 < 32; ++k4) {
                ulonglong2 a = actp[k4 * 32];
#pragma unroll
                for (int r = 0; r < 8; ++r) {
                    ulonglong2 wv = *(const ulonglong2*)&smw[wbase + r * 1024 + k4 * 4];
                    acc[r] = ffma2(a.x, wv.x, acc[r]);
                    acc[r] = ffma2(a.y, wv.y, acc[r]);
                }
            }
#pragma unroll
            for (int r = 0; r < 8; ++r)
                smw[OFF_PART + (rg * 8 + r) * 256 + sp * 32 + lane] = fsum2(acc[r]);
        }
        __syncthreads();
        if (beta < 128) {
            float v = 0.f;
#pragma unroll
            for (int s8 = 0; s8 < 8; ++s8) v += smw[OFF_PART + w * 256 + s8 * 32 + lane];
            smw[OFF_GS + w * 32 + lane] = v;
        }
        __syncthreads();
        if (beta < 128 && w < 4) {
            const int hh = (beta << 2) + w;
            float pg4[4];
#pragma unroll
            for (int g = 0; g < 4; ++g) {
                const int row = g * BH + hh;
                float v = smw[OFF_GS + (g * 4 + w) * 32 + lane] + bx[row];
                v += g_p2a[0][(size_t)row * 32 + lane];
                v += g_p2a[1][(size_t)row * 32 + lane];
                v += g_p2a[2][(size_t)row * 32 + lane];
                v += g_p2a[3][(size_t)row * 32 + lane];
                pg4[g] = v;
            }
            float c1 = g_c1T[hh * 32 + lane];
            float h1v = actF[(hh >> 2) * 128 + lane * 4 + (hh & 3)];
            float c2 = sigf(pg4[1]) * c1 + sigf(pg4[0]) * tanhf(pg4[3]);
            float h2 = sigf(pg4[2]) * tanhf(c2);
            float ym = y_mask[t * BB + lane];
            h2 = ym * h2 + (1.f - ym) * h1v;
            out_hs[(size_t)t * (BB * BH) + lane * BH + hh] = h2;
            out_cs[(size_t)t * (BB * BH) + lane * BH + hh] = c2;
            g_cT[hh * 32 + lane] = c2;
            hT[(hh >> 2) * 128 + lane * 4 + (hh & 3)] = h2;
        }
        gbar(beta);
    }
}

// ---------------- launch ----------------
extern "C" void kernel_launch(void* const* d_in, const int* in_sizes, int n_in,
                              void* d_out, int out_size) {
    const float* y_emb   = (const float*)d_in[0];
    const float* context = (const float*)d_in[1];
    const float* init_h  = (const float*)d_in[2];
    const float* init_c  = (const float*)d_in[3];
    const float* x_mask  = (const float*)d_in[4];
    const float* y_mask  = (const float*)d_in[5];
    const float* W       = (const float*)d_in[6];
    const float* U       = (const float*)d_in[7];
    const float* bvec    = (const float*)d_in[8];
    const float* Wx      = (const float*)d_in[9];
    const float* Ux      = (const float*)d_in[10];
    const float* bx      = (const float*)d_in[11];
    const float* Wc_att  = (const float*)d_in[12];
    const float* b_att   = (const float*)d_in[13];
    const float* Wcomb   = (const float*)d_in[14];
    const float* Uatt    = (const float*)d_in[15];

    cudaFuncSetAttribute(scan_kernel, cudaFuncAttributeMaxDynamicSharedMemorySize, SMEM_BYTES);

    gemm_fused<<<384, 256>>>(context, Wc_att, y_emb, W);

    scan_kernel<<<NBLK, NTHR, SMEM_BYTES>>>(context, init_h, init_c, x_mask, y_mask,
                                            U, bvec, Wx, Ux, bx, b_att, Wcomb, Uatt,
                                            (float*)d_out);
}